// round 1
// baseline (speedup 1.0000x reference)
#include <cuda_runtime.h>

static constexpr int BB  = 4;
static constexpr int SS  = 2048;
static constexpr int DD  = 1024;
static constexpr int HH  = 16;
static constexpr int HSZ = 64;

// Scratch (allowed: __device__ globals, no runtime allocation)
__device__ float g_q[BB * HH * SS * HSZ];
__device__ float g_k[BB * HH * SS * HSZ];
__device__ float g_v[BB * HH * SS * HSZ];
__device__ float g_att[BB * SS * DD];

// ---------------------------------------------------------------------------
// GEMM: C = A @ W^T (+ bias).  A:[M,1024] row-major, W:[N,1024] row-major.
// MODE 0: A = g_att, epilogue adds bias, writes Cout[m*1024+n] (final output).
// MODE 1: A = x, blockIdx.z selects (Wq,Wk,Wv) -> (g_q,g_k,g_v), epilogue
//         scatters into [b,h,s,hs] layout for the attention kernel.
// Tiles: 128x128x16, 256 threads, 8x8 per-thread micro-tile.
// ---------------------------------------------------------------------------
template <int MODE>
__global__ __launch_bounds__(256, 2)
void gemm_kernel(const float* __restrict__ A,
                 const float* __restrict__ W0,
                 const float* __restrict__ W1,
                 const float* __restrict__ W2,
                 const float* __restrict__ bias,
                 float* __restrict__ Cout)
{
    __shared__ float As[16][132];
    __shared__ float Bs[16][132];

    const float* Ain = (MODE == 0) ? (const float*)g_att : A;
    const float* W   = W0;
    float*       dst = Cout;
    if (MODE == 1) {
        const int z = blockIdx.z;
        W   = (z == 0) ? W0 : (z == 1) ? W1 : W2;
        dst = (z == 0) ? g_q : (z == 1) ? g_k : g_v;
    }

    const int tid  = threadIdx.x;
    const int ty   = tid >> 4;        // 0..15
    const int tx   = tid & 15;        // 0..15
    const int brow = blockIdx.x;      // M / 128
    const int bcol = blockIdx.y;      // N / 128

    const int r0 = tid >> 2;          // 0..63
    const int c4 = (tid & 3) << 2;    // 0,4,8,12

    float acc[8][8];
#pragma unroll
    for (int i = 0; i < 8; i++)
#pragma unroll
        for (int j = 0; j < 8; j++) acc[i][j] = 0.f;

    for (int kt = 0; kt < DD; kt += 16) {
#pragma unroll
        for (int hlf = 0; hlf < 2; hlf++) {
            const int r = r0 + hlf * 64;
            float4 av = *reinterpret_cast<const float4*>(
                &Ain[(brow * 128 + r) * DD + kt + c4]);
            As[c4 + 0][r] = av.x; As[c4 + 1][r] = av.y;
            As[c4 + 2][r] = av.z; As[c4 + 3][r] = av.w;
            float4 wv = *reinterpret_cast<const float4*>(
                &W[(bcol * 128 + r) * DD + kt + c4]);
            Bs[c4 + 0][r] = wv.x; Bs[c4 + 1][r] = wv.y;
            Bs[c4 + 2][r] = wv.z; Bs[c4 + 3][r] = wv.w;
        }
        __syncthreads();
#pragma unroll
        for (int k = 0; k < 16; k++) {
            float a[8], b[8];
            *reinterpret_cast<float4*>(&a[0]) =
                *reinterpret_cast<const float4*>(&As[k][ty * 8]);
            *reinterpret_cast<float4*>(&a[4]) =
                *reinterpret_cast<const float4*>(&As[k][ty * 8 + 4]);
            *reinterpret_cast<float4*>(&b[0]) =
                *reinterpret_cast<const float4*>(&Bs[k][tx * 8]);
            *reinterpret_cast<float4*>(&b[4]) =
                *reinterpret_cast<const float4*>(&Bs[k][tx * 8 + 4]);
#pragma unroll
            for (int i = 0; i < 8; i++)
#pragma unroll
                for (int j = 0; j < 8; j++)
                    acc[i][j] = fmaf(a[i], b[j], acc[i][j]);
        }
        __syncthreads();
    }

    if (MODE == 0) {
        const int nb = bcol * 128 + tx * 8;
#pragma unroll
        for (int i = 0; i < 8; i++) {
            const int m = brow * 128 + ty * 8 + i;
#pragma unroll
            for (int jj = 0; jj < 8; jj += 4) {
                float4 v;
                v.x = acc[i][jj + 0] + bias[nb + jj + 0];
                v.y = acc[i][jj + 1] + bias[nb + jj + 1];
                v.z = acc[i][jj + 2] + bias[nb + jj + 2];
                v.w = acc[i][jj + 3] + bias[nb + jj + 3];
                *reinterpret_cast<float4*>(&Cout[m * DD + nb + jj]) = v;
            }
        }
    } else {
        const int nb  = bcol * 128 + tx * 8;   // tx*8..tx*8+7 stays inside one head
        const int h   = nb >> 6;
        const int hs0 = nb & 63;
#pragma unroll
        for (int i = 0; i < 8; i++) {
            const int m  = brow * 128 + ty * 8 + i;
            const int bb = m >> 11;            // m / 2048
            const int s  = m & 2047;
            float* dp = dst + ((bb * HH + h) * SS + s) * HSZ + hs0;
#pragma unroll
            for (int jj = 0; jj < 8; jj += 4) {
                float4 v;
                v.x = acc[i][jj + 0]; v.y = acc[i][jj + 1];
                v.z = acc[i][jj + 2]; v.w = acc[i][jj + 3];
                *reinterpret_cast<float4*>(&dp[jj]) = v;
            }
        }
    }
}

// ---------------------------------------------------------------------------
// Flash attention (fp32, causal). One block per (query-tile, b*h).
// 64 queries x 64-key tiles, HS=64. 256 threads, 4x4 micro-tiles.
// Row stats reduced across the 16 lanes that share a query-row group.
// Writes output directly in [b, s, h*64+d] layout for the output projection.
// ---------------------------------------------------------------------------
__global__ __launch_bounds__(256)
void attn_kernel()
{
    extern __shared__ float sm[];
    float* Qs = sm;               // 64 x 68
    float* Ks = Qs + 64 * 68;     // 64 x 68
    float* Vs = Ks + 64 * 68;     // 64 x 68
    float* Ps = Vs + 64 * 68;     // 64 x 68

    const int qt  = blockIdx.x;   // query tile (0..31)
    const int bh  = blockIdx.y;   // b*16 + h   (0..63)
    const int tid = threadIdx.x;
    const int ty  = tid >> 4;     // query-row group 0..15
    const int tx  = tid & 15;     // key/col group  0..15

    const float* Qg = g_q + bh * SS * HSZ + qt * 64 * HSZ;
    const float* Kg = g_k + bh * SS * HSZ;
    const float* Vg = g_v + bh * SS * HSZ;

    // Load Q tile (row-major, stride 68 for conflict-free float4 access)
#pragma unroll
    for (int u = 0; u < 4; u++) {
        const int idx = tid + 256 * u;
        const int r   = idx >> 4;
        const int cc  = (idx & 15) << 2;
        *reinterpret_cast<float4*>(&Qs[r * 68 + cc]) =
            *reinterpret_cast<const float4*>(&Qg[r * 64 + cc]);
    }

    float mrow[4], lrow[4], o[4][4];
#pragma unroll
    for (int i = 0; i < 4; i++) {
        mrow[i] = -1e30f;   // finite sentinel: exp(-1e30 - x) flushes to 0, no NaN
        lrow[i] = 0.f;
#pragma unroll
        for (int j = 0; j < 4; j++) o[i][j] = 0.f;
    }

    for (int kv = 0; kv <= qt; kv++) {
        if (kv) __syncthreads();   // protect Ks/Vs/Ps against previous iteration readers
        const float* kp = Kg + kv * 64 * HSZ;
        const float* vp = Vg + kv * 64 * HSZ;
#pragma unroll
        for (int u = 0; u < 4; u++) {
            const int idx = tid + 256 * u;
            const int r   = idx >> 4;
            const int cc  = (idx & 15) << 2;
            *reinterpret_cast<float4*>(&Ks[r * 68 + cc]) =
                *reinterpret_cast<const float4*>(&kp[r * 64 + cc]);
            *reinterpret_cast<float4*>(&Vs[r * 68 + cc]) =
                *reinterpret_cast<const float4*>(&vp[r * 64 + cc]);
        }
        __syncthreads();

        // Scores: S = Q K^T (inner product along d, float4-vectorized)
        float sc[4][4];
#pragma unroll
        for (int i = 0; i < 4; i++)
#pragma unroll
            for (int j = 0; j < 4; j++) sc[i][j] = 0.f;

#pragma unroll
        for (int d4 = 0; d4 < 64; d4 += 4) {
            float a[4][4], b[4][4];
#pragma unroll
            for (int i = 0; i < 4; i++)
                *reinterpret_cast<float4*>(a[i]) =
                    *reinterpret_cast<const float4*>(&Qs[(ty * 4 + i) * 68 + d4]);
#pragma unroll
            for (int j = 0; j < 4; j++)
                *reinterpret_cast<float4*>(b[j]) =
                    *reinterpret_cast<const float4*>(&Ks[(tx * 4 + j) * 68 + d4]);
#pragma unroll
            for (int i = 0; i < 4; i++)
#pragma unroll
                for (int j = 0; j < 4; j++) {
                    sc[i][j] = fmaf(a[i][0], b[j][0], sc[i][j]);
                    sc[i][j] = fmaf(a[i][1], b[j][1], sc[i][j]);
                    sc[i][j] = fmaf(a[i][2], b[j][2], sc[i][j]);
                    sc[i][j] = fmaf(a[i][3], b[j][3], sc[i][j]);
                }
        }

        const float scale = 0.125f;  // 1/sqrt(64)
        const bool  diag  = (kv == qt);
#pragma unroll
        for (int i = 0; i < 4; i++)
#pragma unroll
            for (int j = 0; j < 4; j++) {
                sc[i][j] *= scale;
                if (diag && (tx * 4 + j > ty * 4 + i)) sc[i][j] = -1e30f;
            }

        // Online softmax per query row (reduce across the 16-lane tx group)
#pragma unroll
        for (int i = 0; i < 4; i++) {
            float rmax = fmaxf(fmaxf(sc[i][0], sc[i][1]), fmaxf(sc[i][2], sc[i][3]));
#pragma unroll
            for (int off = 1; off < 16; off <<= 1)
                rmax = fmaxf(rmax, __shfl_xor_sync(0xffffffffu, rmax, off));
            const float mnew  = fmaxf(mrow[i], rmax);
            const float alpha = __expf(mrow[i] - mnew);
            float rsum = 0.f;
#pragma unroll
            for (int j = 0; j < 4; j++) {
                const float p = __expf(sc[i][j] - mnew);
                sc[i][j] = p;
                rsum += p;
            }
#pragma unroll
            for (int off = 1; off < 16; off <<= 1)
                rsum += __shfl_xor_sync(0xffffffffu, rsum, off);
            lrow[i] = lrow[i] * alpha + rsum;
            mrow[i] = mnew;
#pragma unroll
            for (int j = 0; j < 4; j++) o[i][j] *= alpha;
            *reinterpret_cast<float4*>(&Ps[(ty * 4 + i) * 68 + tx * 4]) =
                make_float4(sc[i][0], sc[i][1], sc[i][2], sc[i][3]);
        }
        __syncthreads();

        // O += P V
#pragma unroll
        for (int k4 = 0; k4 < 64; k4 += 4) {
            float pa[4][4];
#pragma unroll
            for (int i = 0; i < 4; i++)
                *reinterpret_cast<float4*>(pa[i]) =
                    *reinterpret_cast<const float4*>(&Ps[(ty * 4 + i) * 68 + k4]);
#pragma unroll
            for (int kk = 0; kk < 4; kk++) {
                const float4 vb = *reinterpret_cast<const float4*>(
                    &Vs[(k4 + kk) * 68 + tx * 4]);
#pragma unroll
                for (int i = 0; i < 4; i++) {
                    o[i][0] = fmaf(pa[i][kk], vb.x, o[i][0]);
                    o[i][1] = fmaf(pa[i][kk], vb.y, o[i][1]);
                    o[i][2] = fmaf(pa[i][kk], vb.z, o[i][2]);
                    o[i][3] = fmaf(pa[i][kk], vb.w, o[i][3]);
                }
            }
        }
    }

    // Normalize and write to [b, s, h*64+d] for the output projection
    const int h  = bh & 15;
    const int bb = bh >> 4;
#pragma unroll
    for (int i = 0; i < 4; i++) {
        const int   q   = qt * 64 + ty * 4 + i;
        const float inv = 1.f / lrow[i];
        const float4 v  = make_float4(o[i][0] * inv, o[i][1] * inv,
                                      o[i][2] * inv, o[i][3] * inv);
        *reinterpret_cast<float4*>(&g_att[(bb * SS + q) * DD + h * 64 + tx * 4]) = v;
    }
}

// ---------------------------------------------------------------------------

static constexpr int ATTN_SMEM = 4 * 64 * 68 * (int)sizeof(float);  // 69632 B

extern "C" void kernel_launch(void* const* d_in, const int* in_sizes, int n_in,
                              void* d_out, int out_size)
{
    const float* x  = (const float*)d_in[0];
    const float* Wk = (const float*)d_in[1];
    const float* Wq = (const float*)d_in[2];
    const float* Wv = (const float*)d_in[3];
    const float* Wo = (const float*)d_in[4];
    const float* bo = (const float*)d_in[5];
    float* out = (float*)d_out;

    // Idempotent attribute set (needed: 69.6 KB dynamic smem > 48 KB default)
    cudaFuncSetAttribute(attn_kernel,
                         cudaFuncAttributeMaxDynamicSharedMemorySize, ATTN_SMEM);

    // 1) QKV projections: q/k/v = x @ W^T scattered to [b,h,s,hs]
    gemm_kernel<1><<<dim3(BB * SS / 128, DD / 128, 3), 256>>>(
        x, Wq, Wk, Wv, nullptr, nullptr);

    // 2) Causal flash attention -> g_att in [b,s,d]
    attn_kernel<<<dim3(SS / 64, BB * HH), 256, ATTN_SMEM>>>();

    // 3) Output projection: out = g_att @ Wo^T + bo
    gemm_kernel<0><<<dim3(BB * SS / 128, DD / 128, 1), 256>>>(
        nullptr, Wo, nullptr, nullptr, bo, out);
}

// round 4
// speedup vs baseline: 1.4711x; 1.4711x over previous
#include <cuda_runtime.h>
#include <cstdint>

static constexpr int BB  = 4;
static constexpr int SS  = 2048;
static constexpr int DD  = 1024;
static constexpr int HH  = 16;
static constexpr int HSZ = 64;

// Scratch (allowed: __device__ globals, no runtime allocation)
__device__ float g_q[BB * HH * SS * HSZ];
__device__ float g_k[BB * HH * SS * HSZ];
__device__ float g_v[BB * HH * SS * HSZ];
__device__ float g_att[BB * SS * DD];

// ---------------------------------------------------------------------------
// Helpers (all non-arch-specific: cp.async + mma.sync are sm_80+, valid on
// plain compute_103 — tcgen05 is NOT usable given the harness's PTX target)
// ---------------------------------------------------------------------------
__device__ __forceinline__ uint32_t smem_u32(const void* p) {
    uint32_t a;
    asm("{ .reg .u64 t; cvta.to.shared.u64 t, %1; cvt.u32.u64 %0, t; }"
        : "=r"(a) : "l"(p));
    return a;
}
__device__ __forceinline__ void cp16(uint32_t dst, const void* src) {
    asm volatile("cp.async.cg.shared.global [%0], [%1], 16;"
                 :: "r"(dst), "l"(src));
}
__device__ __forceinline__ void cp_commit() {
    asm volatile("cp.async.commit_group;" ::: "memory");
}
template <int N>
__device__ __forceinline__ void cp_wait() {
    asm volatile("cp.async.wait_group %0;" :: "n"(N) : "memory");
}
__device__ __forceinline__ uint32_t f2tf32(float v) {
    uint32_t t;
    asm("cvt.rna.tf32.f32 %0, %1;" : "=r"(t) : "f"(v));
    return t;
}
__device__ __forceinline__ void mma_tf32(float& c0, float& c1, float& c2, float& c3,
                                         uint32_t a0, uint32_t a1, uint32_t a2, uint32_t a3,
                                         uint32_t b0, uint32_t b1) {
    asm volatile(
        "mma.sync.aligned.m16n8k8.row.col.f32.tf32.tf32.f32 "
        "{%0,%1,%2,%3}, {%4,%5,%6,%7}, {%8,%9}, {%0,%1,%2,%3};"
        : "+f"(c0), "+f"(c1), "+f"(c2), "+f"(c3)
        : "r"(a0), "r"(a1), "r"(a2), "r"(a3), "r"(b0), "r"(b1));
}

// Swizzled float-index within a [rows][32]-float tile stored in 128B rows:
// element (row, col) -> row*32 + ((col>>2) ^ (row&7))*4 + (col&3)
__device__ __forceinline__ int sw_idx(int row, int col) {
    return row * 32 + (((col >> 2) ^ (row & 7)) << 2) + (col & 3);
}

// ---------------------------------------------------------------------------
// tf32 mma.sync GEMM: C = A @ W^T (+bias). A:[M,1024], W:[N,1024] row-major.
// CTA tile 128x128, K-chunk 32, 3-stage cp.async pipeline, 256 threads.
// 8 warps in 2x4: warp tile 64x32 = 4x4 m16n8k8 MMAs per k-step.
// MODE 0: A=g_att, +bias, writes Cout[m*1024+n].
// MODE 1: A=x, blockIdx.z selects W -> scatter into [b,h,s,hs].
// ---------------------------------------------------------------------------
static constexpr int GSTAGES   = 3;
static constexpr int NCHUNK    = 32;                 // 1024 / 32
static constexpr int STAGE_FL  = 2 * 128 * 32;       // A + B floats per stage
static constexpr int GEMM_SMEM = GSTAGES * STAGE_FL * 4;  // 98304 B

template <int MODE>
__global__ __launch_bounds__(256, 2)
void gemm_tc(const float* __restrict__ A,
             const float* __restrict__ W0,
             const float* __restrict__ W1,
             const float* __restrict__ W2,
             const float* __restrict__ bias,
             float* __restrict__ Cout)
{
    extern __shared__ float smf[];
    const uint32_t sbase = smem_u32(smf);

    const int tid  = threadIdx.x;
    const int wid  = tid >> 5;
    const int lane = tid & 31;
    const int gID  = lane >> 2;      // 0..7
    const int ctg  = lane & 3;       // 0..3
    const int wRow = (wid & 1) * 64; // 2 warp-rows
    const int wCol = (wid >> 1) * 32;// 4 warp-cols

    const int brow = blockIdx.x;
    const int bcol = blockIdx.y;

    const float* Ain = (MODE == 0) ? (const float*)g_att : A;
    const float* W   = W0;
    float*       dst = Cout;
    if (MODE == 1) {
        const int z = blockIdx.z;
        W   = (z == 0) ? W0 : (z == 1) ? W1 : W2;
        dst = (z == 0) ? g_q : (z == 1) ? g_k : g_v;
    }

    const float* ap = Ain + (size_t)(brow * 128) * DD;
    const float* wp = W   + (size_t)(bcol * 128) * DD;

    // Staging: 256 threads x 4 cp16 each for A and for B per chunk
    const int ldrow = tid >> 3;        // base row 0..31 (x4 via +32*u)
    const int ldc16 = tid & 7;         // 16B chunk 0..7
    auto load_chunk = [&](int chunk, int stage) {
        const uint32_t aB = sbase + (uint32_t)(stage * STAGE_FL) * 4u;
        const uint32_t bB = aB + 128 * 32 * 4;
        const float* a0 = ap + chunk * 32;
        const float* w0 = wp + chunk * 32;
#pragma unroll
        for (int u = 0; u < 4; u++) {
            const int row = ldrow + 32 * u;
            const uint32_t off =
                (uint32_t)(row * 128 + ((ldc16 ^ (row & 7)) << 4));
            cp16(aB + off, a0 + (size_t)row * DD + ldc16 * 4);
            cp16(bB + off, w0 + (size_t)row * DD + ldc16 * 4);
        }
    };

    float c[4][4][4];
#pragma unroll
    for (int i = 0; i < 4; i++)
#pragma unroll
        for (int j = 0; j < 4; j++)
#pragma unroll
            for (int r = 0; r < 4; r++) c[i][j][r] = 0.f;

    load_chunk(0, 0); cp_commit();
    load_chunk(1, 1); cp_commit();

    int stage = 0;
    for (int i = 0; i < NCHUNK; i++) {
        if (i + 2 < NCHUNK) {
            load_chunk(i + 2, (stage + 2) % GSTAGES);
            cp_commit();
            cp_wait<2>();
        } else {
            cp_wait<0>();
        }
        __syncthreads();

        const float* sA = smf + stage * STAGE_FL;
        const float* sB = sA + 128 * 32;
#pragma unroll
        for (int k0 = 0; k0 < 32; k0 += 8) {
            uint32_t a[4][4], b[4][2];
#pragma unroll
            for (int mt = 0; mt < 4; mt++) {
                const int r0 = wRow + mt * 16 + gID;
                a[mt][0] = f2tf32(sA[sw_idx(r0,     k0 + ctg)]);
                a[mt][1] = f2tf32(sA[sw_idx(r0 + 8, k0 + ctg)]);
                a[mt][2] = f2tf32(sA[sw_idx(r0,     k0 + ctg + 4)]);
                a[mt][3] = f2tf32(sA[sw_idx(r0 + 8, k0 + ctg + 4)]);
            }
#pragma unroll
            for (int nt = 0; nt < 4; nt++) {
                const int rn = wCol + nt * 8 + gID;
                b[nt][0] = f2tf32(sB[sw_idx(rn, k0 + ctg)]);
                b[nt][1] = f2tf32(sB[sw_idx(rn, k0 + ctg + 4)]);
            }
#pragma unroll
            for (int mt = 0; mt < 4; mt++)
#pragma unroll
                for (int nt = 0; nt < 4; nt++)
                    mma_tf32(c[mt][nt][0], c[mt][nt][1], c[mt][nt][2], c[mt][nt][3],
                             a[mt][0], a[mt][1], a[mt][2], a[mt][3],
                             b[nt][0], b[nt][1]);
        }
        __syncthreads();
        stage = (stage + 1) % GSTAGES;
    }

    // Epilogue: thread holds C[r][n], C[r][n+1], C[r+8][n], C[r+8][n+1]
    // with r = wRow + mt*16 + gID, n = wCol + nt*8 + ctg*2.
#pragma unroll
    for (int mt = 0; mt < 4; mt++) {
#pragma unroll
        for (int half = 0; half < 2; half++) {
            const int m = brow * 128 + wRow + mt * 16 + gID + half * 8;
            if (MODE == 0) {
                float* rowp = &Cout[(size_t)m * DD + bcol * 128];
#pragma unroll
                for (int nt = 0; nt < 4; nt++) {
                    const int n = wCol + nt * 8 + ctg * 2;
                    float2 v;
                    v.x = c[mt][nt][half * 2 + 0] + bias[bcol * 128 + n];
                    v.y = c[mt][nt][half * 2 + 1] + bias[bcol * 128 + n + 1];
                    *reinterpret_cast<float2*>(&rowp[n]) = v;
                }
            } else {
                const int bb = m >> 11;
                const int s  = m & 2047;
#pragma unroll
                for (int nt = 0; nt < 4; nt++) {
                    const int n  = bcol * 128 + wCol + nt * 8 + ctg * 2;
                    const int h  = n >> 6;
                    const int hs = n & 63;
                    float2 v;
                    v.x = c[mt][nt][half * 2 + 0];
                    v.y = c[mt][nt][half * 2 + 1];
                    *reinterpret_cast<float2*>(
                        &dst[(((size_t)bb * HH + h) * SS + s) * HSZ + hs]) = v;
                }
            }
        }
    }
}

// ---------------------------------------------------------------------------
// Flash attention (fp32, causal). Known-good from R1 (~1.2 ms).
// ---------------------------------------------------------------------------
__global__ __launch_bounds__(256)
void attn_kernel()
{
    extern __shared__ float sm[];
    float* Qs = sm;               // 64 x 68
    float* Ks = Qs + 64 * 68;
    float* Vs = Ks + 64 * 68;
    float* Ps = Vs + 64 * 68;

    const int qt  = blockIdx.x;
    const int bh  = blockIdx.y;
    const int tid = threadIdx.x;
    const int ty  = tid >> 4;
    const int tx  = tid & 15;

    const float* Qg = g_q + bh * SS * HSZ + qt * 64 * HSZ;
    const float* Kg = g_k + bh * SS * HSZ;
    const float* Vg = g_v + bh * SS * HSZ;

#pragma unroll
    for (int u = 0; u < 4; u++) {
        const int idx = tid + 256 * u;
        const int r   = idx >> 4;
        const int cc  = (idx & 15) << 2;
        *reinterpret_cast<float4*>(&Qs[r * 68 + cc]) =
            *reinterpret_cast<const float4*>(&Qg[r * 64 + cc]);
    }

    float mrow[4], lrow[4], o[4][4];
#pragma unroll
    for (int i = 0; i < 4; i++) {
        mrow[i] = -1e30f;
        lrow[i] = 0.f;
#pragma unroll
        for (int j = 0; j < 4; j++) o[i][j] = 0.f;
    }

    for (int kv = 0; kv <= qt; kv++) {
        if (kv) __syncthreads();
        const float* kp = Kg + kv * 64 * HSZ;
        const float* vp = Vg + kv * 64 * HSZ;
#pragma unroll
        for (int u = 0; u < 4; u++) {
            const int idx = tid + 256 * u;
            const int r   = idx >> 4;
            const int cc  = (idx & 15) << 2;
            *reinterpret_cast<float4*>(&Ks[r * 68 + cc]) =
                *reinterpret_cast<const float4*>(&kp[r * 64 + cc]);
            *reinterpret_cast<float4*>(&Vs[r * 68 + cc]) =
                *reinterpret_cast<const float4*>(&vp[r * 64 + cc]);
        }
        __syncthreads();

        float sc[4][4];
#pragma unroll
        for (int i = 0; i < 4; i++)
#pragma unroll
            for (int j = 0; j < 4; j++) sc[i][j] = 0.f;

#pragma unroll
        for (int d4 = 0; d4 < 64; d4 += 4) {
            float a[4][4], b[4][4];
#pragma unroll
            for (int i = 0; i < 4; i++)
                *reinterpret_cast<float4*>(a[i]) =
                    *reinterpret_cast<const float4*>(&Qs[(ty * 4 + i) * 68 + d4]);
#pragma unroll
            for (int j = 0; j < 4; j++)
                *reinterpret_cast<float4*>(b[j]) =
                    *reinterpret_cast<const float4*>(&Ks[(tx * 4 + j) * 68 + d4]);
#pragma unroll
            for (int i = 0; i < 4; i++)
#pragma unroll
                for (int j = 0; j < 4; j++) {
                    sc[i][j] = fmaf(a[i][0], b[j][0], sc[i][j]);
                    sc[i][j] = fmaf(a[i][1], b[j][1], sc[i][j]);
                    sc[i][j] = fmaf(a[i][2], b[j][2], sc[i][j]);
                    sc[i][j] = fmaf(a[i][3], b[j][3], sc[i][j]);
                }
        }

        const float scale = 0.125f;
        const bool  diag  = (kv == qt);
#pragma unroll
        for (int i = 0; i < 4; i++)
#pragma unroll
            for (int j = 0; j < 4; j++) {
                sc[i][j] *= scale;
                if (diag && (tx * 4 + j > ty * 4 + i)) sc[i][j] = -1e30f;
            }

#pragma unroll
        for (int i = 0; i < 4; i++) {
            float rmax = fmaxf(fmaxf(sc[i][0], sc[i][1]), fmaxf(sc[i][2], sc[i][3]));
#pragma unroll
            for (int off = 1; off < 16; off <<= 1)
                rmax = fmaxf(rmax, __shfl_xor_sync(0xffffffffu, rmax, off));
            const float mnew  = fmaxf(mrow[i], rmax);
            const float alpha = __expf(mrow[i] - mnew);
            float rsum = 0.f;
#pragma unroll
            for (int j = 0; j < 4; j++) {
                const float p = __expf(sc[i][j] - mnew);
                sc[i][j] = p;
                rsum += p;
            }
#pragma unroll
            for (int off = 1; off < 16; off <<= 1)
                rsum += __shfl_xor_sync(0xffffffffu, rsum, off);
            lrow[i] = lrow[i] * alpha + rsum;
            mrow[i] = mnew;
#pragma unroll
            for (int j = 0; j < 4; j++) o[i][j] *= alpha;
            *reinterpret_cast<float4*>(&Ps[(ty * 4 + i) * 68 + tx * 4]) =
                make_float4(sc[i][0], sc[i][1], sc[i][2], sc[i][3]);
        }
        __syncthreads();

#pragma unroll
        for (int k4 = 0; k4 < 64; k4 += 4) {
            float pa[4][4];
#pragma unroll
            for (int i = 0; i < 4; i++)
                *reinterpret_cast<float4*>(pa[i]) =
                    *reinterpret_cast<const float4*>(&Ps[(ty * 4 + i) * 68 + k4]);
#pragma unroll
            for (int kk = 0; kk < 4; kk++) {
                const float4 vb = *reinterpret_cast<const float4*>(
                    &Vs[(k4 + kk) * 68 + tx * 4]);
#pragma unroll
                for (int i = 0; i < 4; i++) {
                    o[i][0] = fmaf(pa[i][kk], vb.x, o[i][0]);
                    o[i][1] = fmaf(pa[i][kk], vb.y, o[i][1]);
                    o[i][2] = fmaf(pa[i][kk], vb.z, o[i][2]);
                    o[i][3] = fmaf(pa[i][kk], vb.w, o[i][3]);
                }
            }
        }
    }

    const int h  = bh & 15;
    const int bb = bh >> 4;
#pragma unroll
    for (int i = 0; i < 4; i++) {
        const int   q   = qt * 64 + ty * 4 + i;
        const float inv = 1.f / lrow[i];
        const float4 v  = make_float4(o[i][0] * inv, o[i][1] * inv,
                                      o[i][2] * inv, o[i][3] * inv);
        *reinterpret_cast<float4*>(&g_att[(bb * SS + q) * DD + h * 64 + tx * 4]) = v;
    }
}

// ---------------------------------------------------------------------------

static constexpr int ATTN_SMEM = 4 * 64 * 68 * (int)sizeof(float);  // 69632 B

extern "C" void kernel_launch(void* const* d_in, const int* in_sizes, int n_in,
                              void* d_out, int out_size)
{
    const float* x  = (const float*)d_in[0];
    const float* Wk = (const float*)d_in[1];
    const float* Wq = (const float*)d_in[2];
    const float* Wv = (const float*)d_in[3];
    const float* Wo = (const float*)d_in[4];
    const float* bo = (const float*)d_in[5];
    float* out = (float*)d_out;

    cudaFuncSetAttribute(attn_kernel,
                         cudaFuncAttributeMaxDynamicSharedMemorySize, ATTN_SMEM);
    cudaFuncSetAttribute(gemm_tc<0>,
                         cudaFuncAttributeMaxDynamicSharedMemorySize, GEMM_SMEM);
    cudaFuncSetAttribute(gemm_tc<1>,
                         cudaFuncAttributeMaxDynamicSharedMemorySize, GEMM_SMEM);

    // 1) QKV projections (tf32 mma.sync): q/k/v = x @ W^T -> [b,h,s,hs]
    gemm_tc<1><<<dim3(BB * SS / 128, DD / 128, 3), 256, GEMM_SMEM>>>(
        x, Wq, Wk, Wv, nullptr, nullptr);

    // 2) Causal flash attention (fp32) -> g_att in [b,s,d]
    attn_kernel<<<dim3(SS / 64, BB * HH), 256, ATTN_SMEM>>>();

    // 3) Output projection (tf32 mma.sync): out = g_att @ Wo^T + bo
    gemm_tc<0><<<dim3(BB * SS / 128, DD / 128, 1), 256, GEMM_SMEM>>>(
        nullptr, Wo, nullptr, nullptr, bo, out);
}

// round 5
// speedup vs baseline: 2.2542x; 1.5323x over previous
#include <cuda_runtime.h>
#include <cstdint>

static constexpr int BB  = 4;
static constexpr int SS  = 2048;
static constexpr int DD  = 1024;
static constexpr int HH  = 16;
static constexpr int HSZ = 64;

// Scratch: hi/lo-split tf32 operands, packed as float2 (hi,lo) pairs.
// g_q4/g_k4: [b*h][s][hs] (2 packed float2 per float4). q pre-scaled by 0.125.
// g_v4: TRANSPOSED [b*h][hs][s] (accessed as float2*).
__device__ float4 g_q4[BB * HH * SS * HSZ / 2];
__device__ float4 g_k4[BB * HH * SS * HSZ / 2];
__device__ float4 g_v4[BB * HH * SS * HSZ / 2];
__device__ float  g_att[BB * SS * DD];

// ---------------------------------------------------------------------------
// Helpers (sm_80-era PTX only: valid on plain compute_103; tcgen05 is not)
// ---------------------------------------------------------------------------
__device__ __forceinline__ uint32_t smem_u32(const void* p) {
    uint32_t a;
    asm("{ .reg .u64 t; cvta.to.shared.u64 t, %1; cvt.u32.u64 %0, t; }"
        : "=r"(a) : "l"(p));
    return a;
}
__device__ __forceinline__ void cp16(uint32_t dst, const void* src) {
    asm volatile("cp.async.cg.shared.global [%0], [%1], 16;"
                 :: "r"(dst), "l"(src));
}
__device__ __forceinline__ void cp_commit() {
    asm volatile("cp.async.commit_group;" ::: "memory");
}
template <int N>
__device__ __forceinline__ void cp_wait() {
    asm volatile("cp.async.wait_group %0;" :: "n"(N) : "memory");
}
__device__ __forceinline__ uint32_t f2tf32(float v) {
    uint32_t t;
    asm("cvt.rna.tf32.f32 %0, %1;" : "=r"(t) : "f"(v));
    return t;
}
__device__ __forceinline__ float tf32r(float v) {      // rna-rounded, as float
    return __uint_as_float(f2tf32(v));
}
__device__ __forceinline__ void mma_tf32(float& c0, float& c1, float& c2, float& c3,
                                         uint32_t a0, uint32_t a1, uint32_t a2, uint32_t a3,
                                         uint32_t b0, uint32_t b1) {
    asm volatile(
        "mma.sync.aligned.m16n8k8.row.col.f32.tf32.tf32.f32 "
        "{%0,%1,%2,%3}, {%4,%5,%6,%7}, {%8,%9}, {%0,%1,%2,%3};"
        : "+f"(c0), "+f"(c1), "+f"(c2), "+f"(c3)
        : "r"(a0), "r"(a1), "r"(a2), "r"(a3), "r"(b0), "r"(b1));
}
__device__ __forceinline__ void mma4(float* c, const uint32_t* a,
                                     uint32_t b0, uint32_t b1) {
    mma_tf32(c[0], c[1], c[2], c[3], a[0], a[1], a[2], a[3], b0, b1);
}

// Swizzled float2-index in a [rows][64]-float2 tile (512B rows):
// granule16 = (col>>1) ^ (row&7)  -> conflict-free for (row varies, col fixed)
__device__ __forceinline__ int sw2(int row, int col) {
    return row * 64 + ((((col >> 1) ^ (row & 7)) << 1) | (col & 1));
}
// Swizzled float-index within a [rows][32]-float tile (128B rows) [GEMM]
__device__ __forceinline__ int sw_idx(int row, int col) {
    return row * 32 + (((col >> 2) ^ (row & 7)) << 2) + (col & 3);
}

// ---------------------------------------------------------------------------
// tf32 mma.sync GEMM (from R4, validated): C = A @ W^T (+bias).
// MODE 0: A=g_att, +bias, writes Cout fp32.
// MODE 1: A=x, z selects W; epilogue hi/lo-splits and scatters:
//         z=0 -> g_q4 (scaled 0.125), z=1 -> g_k4, z=2 -> g_v4 (transposed).
// ---------------------------------------------------------------------------
static constexpr int GSTAGES   = 3;
static constexpr int NCHUNK    = 32;
static constexpr int STAGE_FL  = 2 * 128 * 32;
static constexpr int GEMM_SMEM = GSTAGES * STAGE_FL * 4;  // 98304 B

template <int MODE>
__global__ __launch_bounds__(256, 2)
void gemm_tc(const float* __restrict__ A,
             const float* __restrict__ W0,
             const float* __restrict__ W1,
             const float* __restrict__ W2,
             const float* __restrict__ bias,
             float* __restrict__ Cout)
{
    extern __shared__ float smf[];
    const uint32_t sbase = smem_u32(smf);

    const int tid  = threadIdx.x;
    const int wid  = tid >> 5;
    const int lane = tid & 31;
    const int gID  = lane >> 2;
    const int ctg  = lane & 3;
    const int wRow = (wid & 1) * 64;
    const int wCol = (wid >> 1) * 32;

    const int brow = blockIdx.x;
    const int bcol = blockIdx.y;

    const float* Ain = (MODE == 0) ? (const float*)g_att : A;
    const float* W   = W0;
    if (MODE == 1) {
        const int z = blockIdx.z;
        W = (z == 0) ? W0 : (z == 1) ? W1 : W2;
    }

    const float* ap = Ain + (size_t)(brow * 128) * DD;
    const float* wp = W   + (size_t)(bcol * 128) * DD;

    const int ldrow = tid >> 3;
    const int ldc16 = tid & 7;
    auto load_chunk = [&](int chunk, int stage) {
        const uint32_t aB = sbase + (uint32_t)(stage * STAGE_FL) * 4u;
        const uint32_t bB = aB + 128 * 32 * 4;
        const float* a0 = ap + chunk * 32;
        const float* w0 = wp + chunk * 32;
#pragma unroll
        for (int u = 0; u < 4; u++) {
            const int row = ldrow + 32 * u;
            const uint32_t off =
                (uint32_t)(row * 128 + ((ldc16 ^ (row & 7)) << 4));
            cp16(aB + off, a0 + (size_t)row * DD + ldc16 * 4);
            cp16(bB + off, w0 + (size_t)row * DD + ldc16 * 4);
        }
    };

    float c[4][4][4];
#pragma unroll
    for (int i = 0; i < 4; i++)
#pragma unroll
        for (int j = 0; j < 4; j++)
#pragma unroll
            for (int r = 0; r < 4; r++) c[i][j][r] = 0.f;

    load_chunk(0, 0); cp_commit();
    load_chunk(1, 1); cp_commit();

    int stage = 0;
    for (int i = 0; i < NCHUNK; i++) {
        if (i + 2 < NCHUNK) {
            load_chunk(i + 2, (stage + 2) % GSTAGES);
            cp_commit();
            cp_wait<2>();
        } else {
            cp_wait<0>();
        }
        __syncthreads();

        const float* sA = smf + stage * STAGE_FL;
        const float* sB = sA + 128 * 32;
#pragma unroll
        for (int k0 = 0; k0 < 32; k0 += 8) {
            uint32_t a[4][4], b[4][2];
#pragma unroll
            for (int mt = 0; mt < 4; mt++) {
                const int r0 = wRow + mt * 16 + gID;
                a[mt][0] = f2tf32(sA[sw_idx(r0,     k0 + ctg)]);
                a[mt][1] = f2tf32(sA[sw_idx(r0 + 8, k0 + ctg)]);
                a[mt][2] = f2tf32(sA[sw_idx(r0,     k0 + ctg + 4)]);
                a[mt][3] = f2tf32(sA[sw_idx(r0 + 8, k0 + ctg + 4)]);
            }
#pragma unroll
            for (int nt = 0; nt < 4; nt++) {
                const int rn = wCol + nt * 8 + gID;
                b[nt][0] = f2tf32(sB[sw_idx(rn, k0 + ctg)]);
                b[nt][1] = f2tf32(sB[sw_idx(rn, k0 + ctg + 4)]);
            }
#pragma unroll
            for (int mt = 0; mt < 4; mt++)
#pragma unroll
                for (int nt = 0; nt < 4; nt++)
                    mma_tf32(c[mt][nt][0], c[mt][nt][1], c[mt][nt][2], c[mt][nt][3],
                             a[mt][0], a[mt][1], a[mt][2], a[mt][3],
                             b[nt][0], b[nt][1]);
        }
        __syncthreads();
        stage = (stage + 1) % GSTAGES;
    }

#pragma unroll
    for (int mt = 0; mt < 4; mt++) {
#pragma unroll
        for (int half = 0; half < 2; half++) {
            const int m = brow * 128 + wRow + mt * 16 + gID + half * 8;
            if (MODE == 0) {
                float* rowp = &Cout[(size_t)m * DD + bcol * 128];
#pragma unroll
                for (int nt = 0; nt < 4; nt++) {
                    const int n = wCol + nt * 8 + ctg * 2;
                    float2 v;
                    v.x = c[mt][nt][half * 2 + 0] + bias[bcol * 128 + n];
                    v.y = c[mt][nt][half * 2 + 1] + bias[bcol * 128 + n + 1];
                    *reinterpret_cast<float2*>(&rowp[n]) = v;
                }
            } else {
                const int bb = m >> 11;
                const int s  = m & 2047;
                const int z  = blockIdx.z;
                const float qs = (z == 0) ? 0.125f : 1.0f;
#pragma unroll
                for (int nt = 0; nt < 4; nt++) {
                    const int n  = bcol * 128 + wCol + nt * 8 + ctg * 2;
                    const int h  = n >> 6;
                    const int hs = n & 63;
                    const float v0 = c[mt][nt][half * 2 + 0] * qs;
                    const float v1 = c[mt][nt][half * 2 + 1] * qs;
                    const float h0 = tf32r(v0), l0 = tf32r(v0 - h0);
                    const float h1 = tf32r(v1), l1 = tf32r(v1 - h1);
                    if (z == 2) {
                        float2* vd = (float2*)g_v4;   // [bh][d][s]
                        const size_t base = ((size_t)(bb * HH + h) * HSZ + hs) * SS + s;
                        vd[base]      = make_float2(h0, l0);
                        vd[base + SS] = make_float2(h1, l1);
                    } else {
                        float4* qd = (z == 0) ? g_q4 : g_k4;   // [bh][s][hs]
                        qd[((size_t)(bb * HH + h) * SS + s) * (HSZ / 2) + (hs >> 1)]
                            = make_float4(h0, l0, h1, l1);
                    }
                }
            }
        }
    }
}

// ---------------------------------------------------------------------------
// Tensor-core causal flash attention, tf32 3-MMA split (fp32-accurate).
// CTA: 128 queries (8 warps x m16), KV tiles of 64 keys, 2-stage cp.async.
// smem: K[2][64x64 f2] | V[2][64x64 f2] | P[8 warps][16x64 f2] = 192 KB.
// ---------------------------------------------------------------------------
static constexpr int ATTN_SMEM = 196608;

__global__ __launch_bounds__(256, 1)
void attn_tc()
{
    extern __shared__ char smem[];
    const uint32_t sbase = smem_u32(smem);

    const int tid  = threadIdx.x;
    const int w    = tid >> 5;
    const int lane = tid & 31;
    const int gID  = lane >> 2;
    const int ctg  = lane & 3;

    const int qt = (int)gridDim.x - 1 - (int)blockIdx.x;  // heavy tiles first
    const int bh = blockIdx.y;
    const int q0 = qt * 128;
    const int NT = 2 * qt + 2;

    const char* kgB = (const char*)g_k4 + (size_t)bh * SS * HSZ * 8;
    const char* vgB = (const char*)g_v4 + (size_t)bh * HSZ * SS * 8;

    auto loadKV = [&](int kv, int st) {
        const uint32_t kb = sbase + (uint32_t)st * 32768u;
        const uint32_t vb = sbase + 65536u + (uint32_t)st * 32768u;
        const char* kp = kgB + (size_t)kv * 64 * HSZ * 8;  // [key][d]
        const char* vp = vgB + (size_t)kv * 64 * 8;        // [d][s], col offset
#pragma unroll
        for (int u = 0; u < 8; u++) {
            const int gi  = tid + 256 * u;          // 0..2047
            const int row = gi >> 5;
            const int cg  = gi & 31;
            const uint32_t doff =
                (uint32_t)((row * 64 + ((cg ^ (row & 7)) << 1)) * 8);
            cp16(kb + doff, kp + ((size_t)row * HSZ + cg * 2) * 8);
            cp16(vb + doff, vp + ((size_t)row * SS + cg * 2) * 8);
        }
        cp_commit();
    };

    // Q fragments (hi/lo), loop-invariant. q pre-scaled by 0.125 at the source.
    uint32_t qh[8][4], ql[8][4];
    {
        const float2* qp = (const float2*)g_q4 +
                           ((size_t)bh * SS + q0 + w * 16) * HSZ;
#pragma unroll
        for (int ks = 0; ks < 8; ks++)
#pragma unroll
            for (int i = 0; i < 4; i++) {
                const int r = gID + (i & 1) * 8;
                const int c = ks * 8 + ctg + (i >> 1) * 4;
                const float2 v = qp[r * HSZ + c];
                qh[ks][i] = __float_as_uint(v.x);
                ql[ks][i] = __float_as_uint(v.y);
            }
    }

    float o[8][4];
#pragma unroll
    for (int nt = 0; nt < 8; nt++)
#pragma unroll
        for (int i = 0; i < 4; i++) o[nt][i] = 0.f;
    float m_[2] = {-1e30f, -1e30f};
    float l_[2] = {0.f, 0.f};

    loadKV(0, 0);

    for (int t = 0; t < NT; t++) {
        __syncthreads();                 // prev compute done -> stage free
        if (t + 1 < NT) { loadKV(t + 1, (t + 1) & 1); cp_wait<1>(); }
        else            { cp_wait<0>(); }
        __syncthreads();                 // stage t visible to all

        // warp-level skip of fully-masked tiles (also guarantees no
        // fully-masked row inside computed tiles -> -1e30 sentinel is safe)
        if (t * 64 <= q0 + w * 16 + 15) {
            const float2* Ks = (const float2*)(smem + (t & 1) * 32768);
            const float2* Vs = (const float2*)(smem + 65536 + (t & 1) * 32768);
            float2*       Ps = (float2*)(smem + 131072 + w * 8192);

            // ---- S = Q K^T (3-MMA split) ----
            float s[8][4];
#pragma unroll
            for (int nt = 0; nt < 8; nt++)
#pragma unroll
                for (int i = 0; i < 4; i++) s[nt][i] = 0.f;

#pragma unroll
            for (int nt = 0; nt < 8; nt++)
#pragma unroll
                for (int ks = 0; ks < 8; ks++) {
                    const float2 b0 = Ks[sw2(nt * 8 + gID, ks * 8 + ctg)];
                    const float2 b1 = Ks[sw2(nt * 8 + gID, ks * 8 + ctg + 4)];
                    const uint32_t bh0 = __float_as_uint(b0.x), bl0 = __float_as_uint(b0.y);
                    const uint32_t bh1 = __float_as_uint(b1.x), bl1 = __float_as_uint(b1.y);
                    mma4(s[nt], qh[ks], bh0, bh1);
                    mma4(s[nt], qh[ks], bl0, bl1);
                    mma4(s[nt], ql[ks], bh0, bh1);
                }

            // ---- causal mask (only diagonal tiles) ----
            if (t >= 2 * qt) {
#pragma unroll
                for (int nt = 0; nt < 8; nt++)
#pragma unroll
                    for (int i = 0; i < 4; i++) {
                        const int kg = t * 64 + nt * 8 + 2 * ctg + (i & 1);
                        const int qg = q0 + w * 16 + gID + (i >> 1) * 8;
                        if (kg > qg) s[nt][i] = -1e30f;
                    }
            }

            // ---- online softmax (per row-half), split P -> smem ----
#pragma unroll
            for (int h2 = 0; h2 < 2; h2++) {
                float rm = -1e30f;
#pragma unroll
                for (int nt = 0; nt < 8; nt++)
                    rm = fmaxf(rm, fmaxf(s[nt][2 * h2], s[nt][2 * h2 + 1]));
                rm = fmaxf(rm, __shfl_xor_sync(0xffffffffu, rm, 1));
                rm = fmaxf(rm, __shfl_xor_sync(0xffffffffu, rm, 2));
                const float mn    = fmaxf(m_[h2], rm);
                const float alpha = __expf(m_[h2] - mn);
                m_[h2] = mn;
                float rs = 0.f;
                const int prow = gID + 8 * h2;
#pragma unroll
                for (int nt = 0; nt < 8; nt++) {
                    const float p0 = __expf(s[nt][2 * h2]     - mn);
                    const float p1 = __expf(s[nt][2 * h2 + 1] - mn);
                    rs += p0 + p1;
                    const float ph0 = tf32r(p0), pl0 = tf32r(p0 - ph0);
                    const float ph1 = tf32r(p1), pl1 = tf32r(p1 - ph1);
                    *(float4*)&Ps[sw2(prow, nt * 8 + 2 * ctg)] =
                        make_float4(ph0, pl0, ph1, pl1);
                }
                rs += __shfl_xor_sync(0xffffffffu, rs, 1);
                rs += __shfl_xor_sync(0xffffffffu, rs, 2);
                l_[h2] = l_[h2] * alpha + rs;
#pragma unroll
                for (int nt = 0; nt < 8; nt++) {
                    o[nt][2 * h2]     *= alpha;
                    o[nt][2 * h2 + 1] *= alpha;
                }
            }
            __syncwarp();

            // ---- O += P V (3-MMA split) ----
#pragma unroll
            for (int ks = 0; ks < 8; ks++) {
                uint32_t ah[4], al[4];
#pragma unroll
                for (int i = 0; i < 4; i++) {
                    const int r = gID + (i & 1) * 8;
                    const int c = ks * 8 + ctg + (i >> 1) * 4;
                    const float2 pv = Ps[sw2(r, c)];
                    ah[i] = __float_as_uint(pv.x);
                    al[i] = __float_as_uint(pv.y);
                }
#pragma unroll
                for (int nt = 0; nt < 8; nt++) {
                    const float2 b0 = Vs[sw2(nt * 8 + gID, ks * 8 + ctg)];
                    const float2 b1 = Vs[sw2(nt * 8 + gID, ks * 8 + ctg + 4)];
                    const uint32_t bh0 = __float_as_uint(b0.x), bl0 = __float_as_uint(b0.y);
                    const uint32_t bh1 = __float_as_uint(b1.x), bl1 = __float_as_uint(b1.y);
                    mma4(o[nt], ah, bh0, bh1);
                    mma4(o[nt], ah, bl0, bl1);
                    mma4(o[nt], al, bh0, bh1);
                }
            }
        }
    }

    // ---- normalize, write [b, s, h*64+d] ----
    const int hh = bh & 15;
    const int bb = bh >> 4;
    const float i0 = 1.f / l_[0];
    const float i1 = 1.f / l_[1];
    const int qg0 = q0 + w * 16 + gID;
#pragma unroll
    for (int nt = 0; nt < 8; nt++) {
        const int d0 = hh * 64 + nt * 8 + 2 * ctg;
        *(float2*)&g_att[(size_t)(bb * SS + qg0) * DD + d0] =
            make_float2(o[nt][0] * i0, o[nt][1] * i0);
        *(float2*)&g_att[(size_t)(bb * SS + qg0 + 8) * DD + d0] =
            make_float2(o[nt][2] * i1, o[nt][3] * i1);
    }
}

// ---------------------------------------------------------------------------

extern "C" void kernel_launch(void* const* d_in, const int* in_sizes, int n_in,
                              void* d_out, int out_size)
{
    const float* x  = (const float*)d_in[0];
    const float* Wk = (const float*)d_in[1];
    const float* Wq = (const float*)d_in[2];
    const float* Wv = (const float*)d_in[3];
    const float* Wo = (const float*)d_in[4];
    const float* bo = (const float*)d_in[5];
    float* out = (float*)d_out;

    cudaFuncSetAttribute(attn_tc,
                         cudaFuncAttributeMaxDynamicSharedMemorySize, ATTN_SMEM);
    cudaFuncSetAttribute(gemm_tc<0>,
                         cudaFuncAttributeMaxDynamicSharedMemorySize, GEMM_SMEM);
    cudaFuncSetAttribute(gemm_tc<1>,
                         cudaFuncAttributeMaxDynamicSharedMemorySize, GEMM_SMEM);

    // 1) QKV projections -> hi/lo-split tf32 operands (q scaled, v transposed)
    gemm_tc<1><<<dim3(BB * SS / 128, DD / 128, 3), 256, GEMM_SMEM>>>(
        x, Wq, Wk, Wv, nullptr, nullptr);

    // 2) Tensor-core causal flash attention -> g_att [b,s,d]
    attn_tc<<<dim3(SS / 128, BB * HH), 256, ATTN_SMEM>>>();

    // 3) Output projection: out = g_att @ Wo^T + bo
    gemm_tc<0><<<dim3(BB * SS / 128, DD / 128, 1), 256, GEMM_SMEM>>>(
        nullptr, Wo, nullptr, nullptr, bo, out);
}

// round 6
// speedup vs baseline: 3.5444x; 1.5724x over previous
#include <cuda_runtime.h>
#include <cuda_bf16.h>
#include <cstdint>

static constexpr int BB  = 4;
static constexpr int SS  = 2048;
static constexpr int DD  = 1024;
static constexpr int HH  = 16;
static constexpr int HSZ = 64;

// Scratch. q/k/v as bf16 hi/lo split, layout [b*h][row][128]:
//   cols 0-63 = hi(headdim), cols 64-127 = lo(headdim). Row = 256 B.
//   q rows = query (pre-scaled by 0.125), k rows = key, v rows = key.
__device__ uint16_t g_qs[BB * HH * SS * 128];
__device__ uint16_t g_ks[BB * HH * SS * 128];
__device__ uint16_t g_vs[BB * HH * SS * 128];
__device__ float    g_att[BB * SS * DD];

// ---------------------------------------------------------------------------
// Helpers (sm_80-era PTX only: valid on plain compute_103)
// ---------------------------------------------------------------------------
__device__ __forceinline__ uint32_t smem_u32(const void* p) {
    uint32_t a;
    asm("{ .reg .u64 t; cvta.to.shared.u64 t, %1; cvt.u32.u64 %0, t; }"
        : "=r"(a) : "l"(p));
    return a;
}
__device__ __forceinline__ void cp16(uint32_t dst, const void* src) {
    asm volatile("cp.async.cg.shared.global [%0], [%1], 16;"
                 :: "r"(dst), "l"(src));
}
__device__ __forceinline__ void cp_commit() {
    asm volatile("cp.async.commit_group;" ::: "memory");
}
template <int N>
__device__ __forceinline__ void cp_wait() {
    asm volatile("cp.async.wait_group %0;" :: "n"(N) : "memory");
}
__device__ __forceinline__ uint32_t f2tf32(float v) {
    uint32_t t;
    asm("cvt.rna.tf32.f32 %0, %1;" : "=r"(t) : "f"(v));
    return t;
}
__device__ __forceinline__ void mma_tf32(float& c0, float& c1, float& c2, float& c3,
                                         uint32_t a0, uint32_t a1, uint32_t a2, uint32_t a3,
                                         uint32_t b0, uint32_t b1) {
    asm volatile(
        "mma.sync.aligned.m16n8k8.row.col.f32.tf32.tf32.f32 "
        "{%0,%1,%2,%3}, {%4,%5,%6,%7}, {%8,%9}, {%0,%1,%2,%3};"
        : "+f"(c0), "+f"(c1), "+f"(c2), "+f"(c3)
        : "r"(a0), "r"(a1), "r"(a2), "r"(a3), "r"(b0), "r"(b1));
}
__device__ __forceinline__ void mma16(float* c, const uint32_t* a,
                                      uint32_t b0, uint32_t b1) {
    asm volatile(
        "mma.sync.aligned.m16n8k16.row.col.f32.bf16.bf16.f32 "
        "{%0,%1,%2,%3}, {%4,%5,%6,%7}, {%8,%9}, {%0,%1,%2,%3};"
        : "+f"(c[0]), "+f"(c[1]), "+f"(c[2]), "+f"(c[3])
        : "r"(a[0]), "r"(a[1]), "r"(a[2]), "r"(a[3]), "r"(b0), "r"(b1));
}
__device__ __forceinline__ void ldm4(uint32_t* r, uint32_t a) {
    asm volatile("ldmatrix.sync.aligned.m8n8.x4.shared.b16 {%0,%1,%2,%3}, [%4];"
                 : "=r"(r[0]), "=r"(r[1]), "=r"(r[2]), "=r"(r[3]) : "r"(a));
}
__device__ __forceinline__ void ldm4t(uint32_t* r, uint32_t a) {
    asm volatile("ldmatrix.sync.aligned.m8n8.x4.trans.shared.b16 {%0,%1,%2,%3}, [%4];"
                 : "=r"(r[0]), "=r"(r[1]), "=r"(r[2]), "=r"(r[3]) : "r"(a));
}
// bf16 hi/lo split of two floats, packed (elem0 low bits)
__device__ __forceinline__ void bfsplit2(float v0, float v1,
                                         uint32_t& hi, uint32_t& lo) {
    __nv_bfloat16 h0 = __float2bfloat16_rn(v0);
    __nv_bfloat16 h1 = __float2bfloat16_rn(v1);
    __nv_bfloat16 l0 = __float2bfloat16_rn(v0 - __bfloat162float(h0));
    __nv_bfloat16 l1 = __float2bfloat16_rn(v1 - __bfloat162float(h1));
    hi = (uint32_t)__bfloat16_as_ushort(h0) | ((uint32_t)__bfloat16_as_ushort(h1) << 16);
    lo = (uint32_t)__bfloat16_as_ushort(l0) | ((uint32_t)__bfloat16_as_ushort(l1) << 16);
}
// Swizzled float-index within a [rows][32]-float tile (128B rows) [GEMM]
__device__ __forceinline__ int sw_idx(int row, int col) {
    return row * 32 + (((col >> 2) ^ (row & 7)) << 2) + (col & 3);
}

// ---------------------------------------------------------------------------
// tf32 mma.sync GEMM (validated R4/R5): C = A @ W^T (+bias).
// MODE 0: A=g_att, +bias, writes Cout fp32.
// MODE 1: A=x, z selects W; epilogue bf16-hi/lo-splits into g_qs/g_ks/g_vs
//         (identical [bh][row][hi|lo] layout; q pre-scaled by 0.125).
// ---------------------------------------------------------------------------
static constexpr int GSTAGES   = 3;
static constexpr int NCHUNK    = 32;
static constexpr int STAGE_FL  = 2 * 128 * 32;
static constexpr int GEMM_SMEM = GSTAGES * STAGE_FL * 4;  // 98304 B

template <int MODE>
__global__ __launch_bounds__(256, 2)
void gemm_tc(const float* __restrict__ A,
             const float* __restrict__ W0,
             const float* __restrict__ W1,
             const float* __restrict__ W2,
             const float* __restrict__ bias,
             float* __restrict__ Cout)
{
    extern __shared__ float smf[];
    const uint32_t sbase = smem_u32(smf);

    const int tid  = threadIdx.x;
    const int wid  = tid >> 5;
    const int lane = tid & 31;
    const int gID  = lane >> 2;
    const int ctg  = lane & 3;
    const int wRow = (wid & 1) * 64;
    const int wCol = (wid >> 1) * 32;

    const int brow = blockIdx.x;
    const int bcol = blockIdx.y;

    const float* Ain = (MODE == 0) ? (const float*)g_att : A;
    const float* W   = W0;
    if (MODE == 1) {
        const int z = blockIdx.z;
        W = (z == 0) ? W0 : (z == 1) ? W1 : W2;
    }

    const float* ap = Ain + (size_t)(brow * 128) * DD;
    const float* wp = W   + (size_t)(bcol * 128) * DD;

    const int ldrow = tid >> 3;
    const int ldc16 = tid & 7;
    auto load_chunk = [&](int chunk, int stage) {
        const uint32_t aB = sbase + (uint32_t)(stage * STAGE_FL) * 4u;
        const uint32_t bB = aB + 128 * 32 * 4;
        const float* a0 = ap + chunk * 32;
        const float* w0 = wp + chunk * 32;
#pragma unroll
        for (int u = 0; u < 4; u++) {
            const int row = ldrow + 32 * u;
            const uint32_t off =
                (uint32_t)(row * 128 + ((ldc16 ^ (row & 7)) << 4));
            cp16(aB + off, a0 + (size_t)row * DD + ldc16 * 4);
            cp16(bB + off, w0 + (size_t)row * DD + ldc16 * 4);
        }
    };

    float c[4][4][4];
#pragma unroll
    for (int i = 0; i < 4; i++)
#pragma unroll
        for (int j = 0; j < 4; j++)
#pragma unroll
            for (int r = 0; r < 4; r++) c[i][j][r] = 0.f;

    load_chunk(0, 0); cp_commit();
    load_chunk(1, 1); cp_commit();

    int stage = 0;
    for (int i = 0; i < NCHUNK; i++) {
        if (i + 2 < NCHUNK) {
            load_chunk(i + 2, (stage + 2) % GSTAGES);
            cp_commit();
            cp_wait<2>();
        } else {
            cp_wait<0>();
        }
        __syncthreads();

        const float* sA = smf + stage * STAGE_FL;
        const float* sB = sA + 128 * 32;
#pragma unroll
        for (int k0 = 0; k0 < 32; k0 += 8) {
            uint32_t a[4][4], b[4][2];
#pragma unroll
            for (int mt = 0; mt < 4; mt++) {
                const int r0 = wRow + mt * 16 + gID;
                a[mt][0] = f2tf32(sA[sw_idx(r0,     k0 + ctg)]);
                a[mt][1] = f2tf32(sA[sw_idx(r0 + 8, k0 + ctg)]);
                a[mt][2] = f2tf32(sA[sw_idx(r0,     k0 + ctg + 4)]);
                a[mt][3] = f2tf32(sA[sw_idx(r0 + 8, k0 + ctg + 4)]);
            }
#pragma unroll
            for (int nt = 0; nt < 4; nt++) {
                const int rn = wCol + nt * 8 + gID;
                b[nt][0] = f2tf32(sB[sw_idx(rn, k0 + ctg)]);
                b[nt][1] = f2tf32(sB[sw_idx(rn, k0 + ctg + 4)]);
            }
#pragma unroll
            for (int mt = 0; mt < 4; mt++)
#pragma unroll
                for (int nt = 0; nt < 4; nt++)
                    mma_tf32(c[mt][nt][0], c[mt][nt][1], c[mt][nt][2], c[mt][nt][3],
                             a[mt][0], a[mt][1], a[mt][2], a[mt][3],
                             b[nt][0], b[nt][1]);
        }
        __syncthreads();
        stage = (stage + 1) % GSTAGES;
    }

#pragma unroll
    for (int mt = 0; mt < 4; mt++) {
#pragma unroll
        for (int half = 0; half < 2; half++) {
            const int m = brow * 128 + wRow + mt * 16 + gID + half * 8;
            if (MODE == 0) {
                float* rowp = &Cout[(size_t)m * DD + bcol * 128];
#pragma unroll
                for (int nt = 0; nt < 4; nt++) {
                    const int n = wCol + nt * 8 + ctg * 2;
                    float2 v;
                    v.x = c[mt][nt][half * 2 + 0] + bias[bcol * 128 + n];
                    v.y = c[mt][nt][half * 2 + 1] + bias[bcol * 128 + n + 1];
                    *reinterpret_cast<float2*>(&rowp[n]) = v;
                }
            } else {
                const int bb = m >> 11;
                const int s  = m & 2047;
                const int z  = blockIdx.z;
                uint16_t* dst = (z == 0) ? g_qs : (z == 1) ? g_ks : g_vs;
                const float qs = (z == 0) ? 0.125f : 1.0f;
#pragma unroll
                for (int nt = 0; nt < 4; nt++) {
                    const int n  = bcol * 128 + wCol + nt * 8 + ctg * 2;
                    const int h  = n >> 6;
                    const int hs = n & 63;
                    uint32_t hi, lo;
                    bfsplit2(c[mt][nt][half * 2 + 0] * qs,
                             c[mt][nt][half * 2 + 1] * qs, hi, lo);
                    const size_t base =
                        ((size_t)(bb * HH + h) * SS + s) * 128 + hs;
                    *(uint32_t*)&dst[base]      = hi;
                    *(uint32_t*)&dst[base + 64] = lo;
                }
            }
        }
    }
}

// ---------------------------------------------------------------------------
// Causal flash attention, bf16 Karatsuba split on tensor cores.
// CTA: 128 queries (8 warps x m16), 64-key tiles, 2-stage cp.async.
// smem: K[2][64x256B] | V[2][64x256B] | PQ[8 warps][16x256B] = 96 KB.
// Per 16x8 output, K=64: main hi*hi (4 k16 MMAs) + corr concat (8) = 12 MMAs.
// ---------------------------------------------------------------------------
static constexpr int ATTN_SMEM = 98304;

__global__ __launch_bounds__(256)
void attn_tc()
{
    extern __shared__ char smem[];
    const uint32_t sbase = smem_u32(smem);

    const int tid  = threadIdx.x;
    const int w    = tid >> 5;
    const int lane = tid & 31;
    const int gID  = lane >> 2;
    const int ctg  = lane & 3;

    const int qt = (int)gridDim.x - 1 - (int)blockIdx.x;  // heavy tiles first
    const int bh = blockIdx.y;
    const int q0 = qt * 128;
    const int NT = 2 * qt + 2;

    const char* kgB = (const char*)g_ks + (size_t)bh * SS * 256;
    const char* vgB = (const char*)g_vs + (size_t)bh * SS * 256;
    const char* qgB = (const char*)g_qs + (size_t)(bh * SS + q0 + w * 16) * 256;

    const uint32_t PsB   = sbase + 65536u + (uint32_t)w * 4096u;
    const int      Psoff = 65536 + w * 4096;      // for direct pointer stores

    // per-lane ldmatrix address components
    const int rB   = lane & 7;          // row-within-8
    const int hB   = (lane >> 3) & 1;   // matrix half
    const int sB   = lane >> 4;         // pair selector
    const int rA   = lane & 15;

    auto loadKV = [&](int t, int st) {
        const uint32_t kb = sbase + (uint32_t)st * 16384u;
        const uint32_t vb = sbase + 32768u + (uint32_t)st * 16384u;
        const char* kp = kgB + (size_t)t * 64 * 256;
        const char* vp = vgB + (size_t)t * 64 * 256;
#pragma unroll
        for (int u = 0; u < 4; u++) {
            const int gi = tid + 256 * u;
            const int row = gi >> 4, ch = gi & 15;
            const uint32_t off = (uint32_t)(row * 256 + ((ch ^ (row & 7)) << 4));
            cp16(kb + off, kp + row * 256 + ch * 16);
            cp16(vb + off, vp + row * 256 + ch * 16);
        }
        cp_commit();
    };

    loadKV(0, 0);
    // stage Q through this warp's P region
#pragma unroll
    for (int u = 0; u < 8; u++) {
        const int idx = lane + 32 * u;
        const int row = idx >> 4, ch = idx & 15;
        const uint32_t off = (uint32_t)(row * 256 + ((ch ^ (row & 7)) << 4));
        cp16(PsB + off, qgB + row * 256 + ch * 16);
    }
    cp_commit();
    cp_wait<0>();
    __syncwarp();

    // Q fragments: blocks 0-3 = qh, 4-7 = ql (A-pattern ldmatrix)
    uint32_t qf[8][4];
#pragma unroll
    for (int j = 0; j < 8; j++)
        ldm4(qf[j], PsB + (uint32_t)(rA * 256 + (((2 * j + sB) ^ (rA & 7)) << 4)));
    __syncthreads();    // KV tile 0 visible to all warps

    float o[8][4];
#pragma unroll
    for (int nt = 0; nt < 8; nt++)
#pragma unroll
        for (int i = 0; i < 4; i++) o[nt][i] = 0.f;
    float m_[2] = {-1e30f, -1e30f};
    float l_[2] = {0.f, 0.f};

    for (int t = 0; t < NT; t++) {
        if (t) __syncthreads();          // guard buffer reuse
        if (t + 1 < NT) { loadKV(t + 1, (t + 1) & 1); cp_wait<1>(); }
        else            { cp_wait<0>(); }
        __syncthreads();                 // stage t visible

        if (t * 64 <= q0 + w * 16 + 15) {
            const uint32_t kst = sbase + (uint32_t)(t & 1) * 16384u;
            const uint32_t vst = sbase + 32768u + (uint32_t)(t & 1) * 16384u;

            // ---- S = Q K^T : kh*(qh+ql) + kl*qh ----
            float s[8][4];
#pragma unroll
            for (int nt = 0; nt < 8; nt++)
#pragma unroll
                for (int i = 0; i < 4; i++) s[nt][i] = 0.f;

#pragma unroll
            for (int ntp = 0; ntp < 4; ntp++) {
                const uint32_t ntb = kst + (uint32_t)((2 * ntp + sB) * 2048 + rB * 256);
#pragma unroll
                for (int j = 0; j < 4; j++) {
                    uint32_t kh_[4], kl_[4];
                    const int ch = 2 * j + hB;
                    ldm4(kh_, ntb + (uint32_t)((ch ^ rB) << 4));
                    ldm4(kl_, ntb + (uint32_t)(((8 + ch) ^ rB) << 4));
                    const int nt = 2 * ntp;
                    mma16(s[nt],     qf[j],     kh_[0], kh_[1]);
                    mma16(s[nt],     qf[4 + j], kh_[0], kh_[1]);
                    mma16(s[nt],     qf[j],     kl_[0], kl_[1]);
                    mma16(s[nt + 1], qf[j],     kh_[2], kh_[3]);
                    mma16(s[nt + 1], qf[4 + j], kh_[2], kh_[3]);
                    mma16(s[nt + 1], qf[j],     kl_[2], kl_[3]);
                }
            }

            // ---- causal mask (diagonal tiles only) ----
            if (t >= 2 * qt) {
#pragma unroll
                for (int nt = 0; nt < 8; nt++)
#pragma unroll
                    for (int i = 0; i < 4; i++) {
                        const int kg = t * 64 + nt * 8 + 2 * ctg + (i & 1);
                        const int qg = q0 + w * 16 + gID + (i >> 1) * 8;
                        if (kg > qg) s[nt][i] = -1e30f;
                    }
            }

            // ---- online softmax; P split to smem as [ph(64)|pl(64)] bf16 ----
#pragma unroll
            for (int h2 = 0; h2 < 2; h2++) {
                float rm = -1e30f;
#pragma unroll
                for (int nt = 0; nt < 8; nt++)
                    rm = fmaxf(rm, fmaxf(s[nt][2 * h2], s[nt][2 * h2 + 1]));
                rm = fmaxf(rm, __shfl_xor_sync(0xffffffffu, rm, 1));
                rm = fmaxf(rm, __shfl_xor_sync(0xffffffffu, rm, 2));
                const float mn    = fmaxf(m_[h2], rm);
                const float alpha = __expf(m_[h2] - mn);
                m_[h2] = mn;
                float rs = 0.f;
                const int prow = gID + 8 * h2;
                const int pr7  = prow & 7;
                char* prp = smem + Psoff + prow * 256 + ctg * 4;
#pragma unroll
                for (int nt = 0; nt < 8; nt++) {
                    const float p0 = __expf(s[nt][2 * h2]     - mn);
                    const float p1 = __expf(s[nt][2 * h2 + 1] - mn);
                    rs += p0 + p1;
                    uint32_t hi, lo;
                    bfsplit2(p0, p1, hi, lo);
                    *(uint32_t*)(prp + ((nt ^ pr7) << 4))       = hi;
                    *(uint32_t*)(prp + (((8 + nt) ^ pr7) << 4)) = lo;
                }
                rs += __shfl_xor_sync(0xffffffffu, rs, 1);
                rs += __shfl_xor_sync(0xffffffffu, rs, 2);
                l_[h2] = l_[h2] * alpha + rs;
#pragma unroll
                for (int nt = 0; nt < 8; nt++) {
                    o[nt][2 * h2]     *= alpha;
                    o[nt][2 * h2 + 1] *= alpha;
                }
            }
            __syncwarp();

            // ---- O += P V : vh*(ph+pl) + vl*ph  (V via ldmatrix.trans) ----
#pragma unroll
            for (int j = 0; j < 4; j++) {
                uint32_t ph_[4], pl_[4];
                ldm4(ph_, PsB + (uint32_t)(rA * 256 + (((2 * j + sB) ^ (rA & 7)) << 4)));
                ldm4(pl_, PsB + (uint32_t)(rA * 256 + (((8 + 2 * j + sB) ^ (rA & 7)) << 4)));
                const uint32_t jrow = vst + (uint32_t)((2 * j + hB) * 2048 + rB * 256);
#pragma unroll
                for (int ntp = 0; ntp < 4; ntp++) {
                    uint32_t vh_[4], vl_[4];
                    const int cv = 2 * ntp + sB;
                    ldm4t(vh_, jrow + (uint32_t)((cv ^ rB) << 4));
                    ldm4t(vl_, jrow + (uint32_t)(((8 + cv) ^ rB) << 4));
                    const int nt = 2 * ntp;
                    mma16(o[nt],     ph_, vh_[0], vh_[1]);
                    mma16(o[nt],     pl_, vh_[0], vh_[1]);
                    mma16(o[nt],     ph_, vl_[0], vl_[1]);
                    mma16(o[nt + 1], ph_, vh_[2], vh_[3]);
                    mma16(o[nt + 1], pl_, vh_[2], vh_[3]);
                    mma16(o[nt + 1], ph_, vl_[2], vl_[3]);
                }
            }
        }
    }

    // ---- normalize, write [b, s, h*64+d] ----
    const int hh = bh & 15;
    const int bb = bh >> 4;
    const float i0 = 1.f / l_[0];
    const float i1 = 1.f / l_[1];
    const int qg0 = q0 + w * 16 + gID;
#pragma unroll
    for (int nt = 0; nt < 8; nt++) {
        const int d0 = hh * 64 + nt * 8 + 2 * ctg;
        *(float2*)&g_att[(size_t)(bb * SS + qg0) * DD + d0] =
            make_float2(o[nt][0] * i0, o[nt][1] * i0);
        *(float2*)&g_att[(size_t)(bb * SS + qg0 + 8) * DD + d0] =
            make_float2(o[nt][2] * i1, o[nt][3] * i1);
    }
}

// ---------------------------------------------------------------------------

extern "C" void kernel_launch(void* const* d_in, const int* in_sizes, int n_in,
                              void* d_out, int out_size)
{
    const float* x  = (const float*)d_in[0];
    const float* Wk = (const float*)d_in[1];
    const float* Wq = (const float*)d_in[2];
    const float* Wv = (const float*)d_in[3];
    const float* Wo = (const float*)d_in[4];
    const float* bo = (const float*)d_in[5];
    float* out = (float*)d_out;

    cudaFuncSetAttribute(attn_tc,
                         cudaFuncAttributeMaxDynamicSharedMemorySize, ATTN_SMEM);
    cudaFuncSetAttribute(gemm_tc<0>,
                         cudaFuncAttributeMaxDynamicSharedMemorySize, GEMM_SMEM);
    cudaFuncSetAttribute(gemm_tc<1>,
                         cudaFuncAttributeMaxDynamicSharedMemorySize, GEMM_SMEM);

    // 1) QKV projections -> bf16 hi/lo split operands (q pre-scaled 0.125)
    gemm_tc<1><<<dim3(BB * SS / 128, DD / 128, 3), 256, GEMM_SMEM>>>(
        x, Wq, Wk, Wv, nullptr, nullptr);

    // 2) Tensor-core causal flash attention (bf16 Karatsuba) -> g_att [b,s,d]
    attn_tc<<<dim3(SS / 128, BB * HH), 256, ATTN_SMEM>>>();

    // 3) Output projection: out = g_att @ Wo^T + bo
    gemm_tc<0><<<dim3(BB * SS / 128, DD / 128, 1), 256, GEMM_SMEM>>>(
        nullptr, Wo, nullptr, nullptr, bo, out);
}

// round 7
// speedup vs baseline: 4.2584x; 1.2014x over previous
#include <cuda_runtime.h>
#include <cuda_bf16.h>
#include <cstdint>

static constexpr int BB  = 4;
static constexpr int SS  = 2048;
static constexpr int DD  = 1024;
static constexpr int HH  = 16;
static constexpr int HSZ = 64;

// Scratch. q/k/v as bf16 hi/lo split, layout [b*h][row][128]:
//   cols 0-63 = hi(headdim), cols 64-127 = lo(headdim). Row = 256 B.
__device__ uint16_t g_qs[BB * HH * SS * 128];
__device__ uint16_t g_ks[BB * HH * SS * 128];
__device__ uint16_t g_vs[BB * HH * SS * 128];
__device__ float    g_att[BB * SS * DD];     // attention out, tf32-pre-rounded
__device__ float    g_xr[BB * SS * DD];      // x, tf32-pre-rounded
__device__ float    g_wr[4 * DD * DD];       // Wq|Wk|Wv|Wo, tf32-pre-rounded

// ---------------------------------------------------------------------------
// Helpers (sm_80-era PTX only: valid on plain compute_103)
// ---------------------------------------------------------------------------
__device__ __forceinline__ uint32_t smem_u32(const void* p) {
    uint32_t a;
    asm("{ .reg .u64 t; cvta.to.shared.u64 t, %1; cvt.u32.u64 %0, t; }"
        : "=r"(a) : "l"(p));
    return a;
}
__device__ __forceinline__ void cp16(uint32_t dst, const void* src) {
    asm volatile("cp.async.cg.shared.global [%0], [%1], 16;"
                 :: "r"(dst), "l"(src));
}
__device__ __forceinline__ void cp_commit() {
    asm volatile("cp.async.commit_group;" ::: "memory");
}
template <int N>
__device__ __forceinline__ void cp_wait() {
    asm volatile("cp.async.wait_group %0;" :: "n"(N) : "memory");
}
__device__ __forceinline__ float tf32r(float v) {
    uint32_t t;
    asm("cvt.rna.tf32.f32 %0, %1;" : "=r"(t) : "f"(v));
    return __uint_as_float(t);
}
__device__ __forceinline__ void mma_tf32(float& c0, float& c1, float& c2, float& c3,
                                         uint32_t a0, uint32_t a1, uint32_t a2, uint32_t a3,
                                         uint32_t b0, uint32_t b1) {
    asm volatile(
        "mma.sync.aligned.m16n8k8.row.col.f32.tf32.tf32.f32 "
        "{%0,%1,%2,%3}, {%4,%5,%6,%7}, {%8,%9}, {%0,%1,%2,%3};"
        : "+f"(c0), "+f"(c1), "+f"(c2), "+f"(c3)
        : "r"(a0), "r"(a1), "r"(a2), "r"(a3), "r"(b0), "r"(b1));
}
__device__ __forceinline__ void mma16(float* c, const uint32_t* a,
                                      uint32_t b0, uint32_t b1) {
    asm volatile(
        "mma.sync.aligned.m16n8k16.row.col.f32.bf16.bf16.f32 "
        "{%0,%1,%2,%3}, {%4,%5,%6,%7}, {%8,%9}, {%0,%1,%2,%3};"
        : "+f"(c[0]), "+f"(c[1]), "+f"(c[2]), "+f"(c[3])
        : "r"(a[0]), "r"(a[1]), "r"(a[2]), "r"(a[3]), "r"(b0), "r"(b1));
}
__device__ __forceinline__ void ldm4(uint32_t* r, uint32_t a) {
    asm volatile("ldmatrix.sync.aligned.m8n8.x4.shared.b16 {%0,%1,%2,%3}, [%4];"
                 : "=r"(r[0]), "=r"(r[1]), "=r"(r[2]), "=r"(r[3]) : "r"(a));
}
__device__ __forceinline__ void ldm4t(uint32_t* r, uint32_t a) {
    asm volatile("ldmatrix.sync.aligned.m8n8.x4.trans.shared.b16 {%0,%1,%2,%3}, [%4];"
                 : "=r"(r[0]), "=r"(r[1]), "=r"(r[2]), "=r"(r[3]) : "r"(a));
}
// bf16 hi/lo split of two floats, packed (elem0 low bits)
__device__ __forceinline__ void bfsplit2(float v0, float v1,
                                         uint32_t& hi, uint32_t& lo) {
    __nv_bfloat16 h0 = __float2bfloat16_rn(v0);
    __nv_bfloat16 h1 = __float2bfloat16_rn(v1);
    __nv_bfloat16 l0 = __float2bfloat16_rn(v0 - __bfloat162float(h0));
    __nv_bfloat16 l1 = __float2bfloat16_rn(v1 - __bfloat162float(h1));
    hi = (uint32_t)__bfloat16_as_ushort(h0) | ((uint32_t)__bfloat16_as_ushort(h1) << 16);
    lo = (uint32_t)__bfloat16_as_ushort(l0) | ((uint32_t)__bfloat16_as_ushort(l1) << 16);
}

// ---------------------------------------------------------------------------
// Pre-rounding: x and the four W matrices -> tf32-rounded fp32 copies.
// One float4 per thread; 12,582,912 floats total = 3,145,728 float4.
// ---------------------------------------------------------------------------
__global__ __launch_bounds__(256)
void round_conv(const float* __restrict__ x,  const float* __restrict__ Wq,
                const float* __restrict__ Wk, const float* __restrict__ Wv,
                const float* __restrict__ Wo)
{
    const int idx = blockIdx.x * 256 + threadIdx.x;
    const float4* src;
    float4* dst;
    if (idx < 2097152) {                       // x: 8,388,608 floats
        src = (const float4*)x + idx;
        dst = (float4*)g_xr + idx;
    } else {
        const int wi  = idx - 2097152;
        const int z   = wi >> 18;              // 262,144 float4 per W
        const int off = wi & 262143;
        const float* w = (z == 0) ? Wq : (z == 1) ? Wk : (z == 2) ? Wv : Wo;
        src = (const float4*)w + off;
        dst = (float4*)g_wr + (size_t)z * 262144 + off;
    }
    float4 v = *src;
    v.x = tf32r(v.x); v.y = tf32r(v.y); v.z = tf32r(v.z); v.w = tf32r(v.w);
    *dst = v;
}

// ---------------------------------------------------------------------------
// tf32 mma.sync GEMM, ldmatrix fragment feed. C = A @ W^T (+bias).
// Inputs pre-rounded to tf32 -> no cvt in the hot loop; fragments via LDSM
// (tf32 m16n8k8 thread map (lane>>2, lane&3) == ldmatrix b16 map on f32 pairs).
// MODE 0: A=g_att, W=g_wr[3], +bias, writes Cout fp32.
// MODE 1: A=g_xr, z selects g_wr[z]; epilogue bf16-splits into g_qs/ks/vs.
// ---------------------------------------------------------------------------
static constexpr int GSTAGES   = 3;
static constexpr int NCHUNK    = 32;
static constexpr int STAGE_FL  = 2 * 128 * 32;
static constexpr int GEMM_SMEM = GSTAGES * STAGE_FL * 4;  // 98304 B

template <int MODE>
__global__ __launch_bounds__(256, 2)
void gemm_tc(const float* __restrict__ bias, float* __restrict__ Cout)
{
    extern __shared__ float smf[];
    const uint32_t sbase = smem_u32(smf);

    const int tid  = threadIdx.x;
    const int wid  = tid >> 5;
    const int lane = tid & 31;
    const int gID  = lane >> 2;
    const int ctg  = lane & 3;
    const int wRow = (wid & 1) * 64;
    const int wCol = (wid >> 1) * 32;

    const int brow = blockIdx.x;
    const int bcol = blockIdx.y;
    const int z    = (MODE == 0) ? 3 : blockIdx.z;

    const float* Ain = (MODE == 0) ? (const float*)g_att : (const float*)g_xr;
    const float* ap  = Ain + (size_t)(brow * 128) * DD;
    const float* wp  = (const float*)g_wr + (size_t)z * (DD * DD)
                     + (size_t)(bcol * 128) * DD;

    const int ldrow = tid >> 3;
    const int ldc16 = tid & 7;
    auto load_chunk = [&](int chunk, int stage) {
        const uint32_t aB = sbase + (uint32_t)(stage * STAGE_FL) * 4u;
        const uint32_t bB = aB + 128 * 32 * 4;
        const float* a0 = ap + chunk * 32;
        const float* w0 = wp + chunk * 32;
#pragma unroll
        for (int u = 0; u < 4; u++) {
            const int row = ldrow + 32 * u;
            const uint32_t off =
                (uint32_t)(row * 128 + ((ldc16 ^ (row & 7)) << 4));
            cp16(aB + off, a0 + (size_t)row * DD + ldc16 * 4);
            cp16(bB + off, w0 + (size_t)row * DD + ldc16 * 4);
        }
    };

    // ldmatrix lane constants (x7 = row&7 for all relevant rows)
    const int x7  = lane & 7;
    const int aro = x7 + ((lane >> 3) & 1) * 8;   // A row-in-16, matrices 0/1
    const int ags = lane >> 4;                    // A granule sel (k half)
    const int bro = x7 + (lane >> 4) * 8;         // B row-in-16 (nt pair)
    const int bgs = (lane >> 3) & 1;              // B granule sel

    float c[4][4][4];
#pragma unroll
    for (int i = 0; i < 4; i++)
#pragma unroll
        for (int j = 0; j < 4; j++)
#pragma unroll
            for (int r = 0; r < 4; r++) c[i][j][r] = 0.f;

    load_chunk(0, 0); cp_commit();
    load_chunk(1, 1); cp_commit();

    int stage = 0;
    for (int i = 0; i < NCHUNK; i++) {
        if (i + 2 < NCHUNK) {
            load_chunk(i + 2, (stage + 2) % GSTAGES);
            cp_commit();
            cp_wait<2>();
        } else {
            cp_wait<0>();
        }
        __syncthreads();

        const uint32_t sA = sbase + (uint32_t)(stage * STAGE_FL) * 4u;
        const uint32_t sB = sA + 128 * 32 * 4;
        uint32_t aBase[4], bBase[2];
#pragma unroll
        for (int mt = 0; mt < 4; mt++)
            aBase[mt] = sA + (uint32_t)((wRow + mt * 16 + aro) * 128);
#pragma unroll
        for (int ntp = 0; ntp < 2; ntp++)
            bBase[ntp] = sB + (uint32_t)((wCol + ntp * 16 + bro) * 128);

#pragma unroll
        for (int ks = 0; ks < 4; ks++) {
            uint32_t a[4][4], b[2][4];
            const uint32_t offA = (uint32_t)(((2 * ks + ags) ^ x7) << 4);
            const uint32_t offB = (uint32_t)(((2 * ks + bgs) ^ x7) << 4);
#pragma unroll
            for (int mt = 0; mt < 4; mt++) ldm4(a[mt], aBase[mt] + offA);
#pragma unroll
            for (int ntp = 0; ntp < 2; ntp++) ldm4(b[ntp], bBase[ntp] + offB);
#pragma unroll
            for (int mt = 0; mt < 4; mt++)
#pragma unroll
                for (int ntp = 0; ntp < 2; ntp++) {
                    mma_tf32(c[mt][2*ntp][0], c[mt][2*ntp][1],
                             c[mt][2*ntp][2], c[mt][2*ntp][3],
                             a[mt][0], a[mt][1], a[mt][2], a[mt][3],
                             b[ntp][0], b[ntp][1]);
                    mma_tf32(c[mt][2*ntp+1][0], c[mt][2*ntp+1][1],
                             c[mt][2*ntp+1][2], c[mt][2*ntp+1][3],
                             a[mt][0], a[mt][1], a[mt][2], a[mt][3],
                             b[ntp][2], b[ntp][3]);
                }
        }
        __syncthreads();
        stage = (stage + 1) % GSTAGES;
    }

#pragma unroll
    for (int mt = 0; mt < 4; mt++) {
#pragma unroll
        for (int half = 0; half < 2; half++) {
            const int m = brow * 128 + wRow + mt * 16 + gID + half * 8;
            if (MODE == 0) {
                float* rowp = &Cout[(size_t)m * DD + bcol * 128];
#pragma unroll
                for (int nt = 0; nt < 4; nt++) {
                    const int n = wCol + nt * 8 + ctg * 2;
                    float2 v;
                    v.x = c[mt][nt][half * 2 + 0] + bias[bcol * 128 + n];
                    v.y = c[mt][nt][half * 2 + 1] + bias[bcol * 128 + n + 1];
                    *reinterpret_cast<float2*>(&rowp[n]) = v;
                }
            } else {
                const int bb = m >> 11;
                const int s  = m & 2047;
                uint16_t* dst = (z == 0) ? g_qs : (z == 1) ? g_ks : g_vs;
                const float qs = (z == 0) ? 0.125f : 1.0f;
#pragma unroll
                for (int nt = 0; nt < 4; nt++) {
                    const int n  = bcol * 128 + wCol + nt * 8 + ctg * 2;
                    const int h  = n >> 6;
                    const int hs = n & 63;
                    uint32_t hi, lo;
                    bfsplit2(c[mt][nt][half * 2 + 0] * qs,
                             c[mt][nt][half * 2 + 1] * qs, hi, lo);
                    const size_t base =
                        ((size_t)(bb * HH + h) * SS + s) * 128 + hs;
                    *(uint32_t*)&dst[base]      = hi;
                    *(uint32_t*)&dst[base + 64] = lo;
                }
            }
        }
    }
}

// ---------------------------------------------------------------------------
// Causal flash attention, bf16 Karatsuba split on tensor cores (R6-validated).
// CTA: 128 queries (8 warps x m16), 64-key tiles, 2-stage cp.async.
// smem: K[2][64x256B] | V[2][64x256B] | PQ[8 warps][16x256B] = 96 KB.
// Epilogue now writes tf32-pre-rounded values for the output GEMM's LDSM path.
// ---------------------------------------------------------------------------
static constexpr int ATTN_SMEM = 98304;

__global__ __launch_bounds__(256)
void attn_tc()
{
    extern __shared__ char smem[];
    const uint32_t sbase = smem_u32(smem);

    const int tid  = threadIdx.x;
    const int w    = tid >> 5;
    const int lane = tid & 31;
    const int gID  = lane >> 2;
    const int ctg  = lane & 3;

    const int qt = (int)gridDim.x - 1 - (int)blockIdx.x;  // heavy tiles first
    const int bh = blockIdx.y;
    const int q0 = qt * 128;
    const int NT = 2 * qt + 2;

    const char* kgB = (const char*)g_ks + (size_t)bh * SS * 256;
    const char* vgB = (const char*)g_vs + (size_t)bh * SS * 256;
    const char* qgB = (const char*)g_qs + (size_t)(bh * SS + q0 + w * 16) * 256;

    const uint32_t PsB   = sbase + 65536u + (uint32_t)w * 4096u;
    const int      Psoff = 65536 + w * 4096;

    const int rB = lane & 7;
    const int hB = (lane >> 3) & 1;
    const int sB = lane >> 4;
    const int rA = lane & 15;

    auto loadKV = [&](int t, int st) {
        const uint32_t kb = sbase + (uint32_t)st * 16384u;
        const uint32_t vb = sbase + 32768u + (uint32_t)st * 16384u;
        const char* kp = kgB + (size_t)t * 64 * 256;
        const char* vp = vgB + (size_t)t * 64 * 256;
#pragma unroll
        for (int u = 0; u < 4; u++) {
            const int gi = tid + 256 * u;
            const int row = gi >> 4, ch = gi & 15;
            const uint32_t off = (uint32_t)(row * 256 + ((ch ^ (row & 7)) << 4));
            cp16(kb + off, kp + row * 256 + ch * 16);
            cp16(vb + off, vp + row * 256 + ch * 16);
        }
        cp_commit();
    };

    loadKV(0, 0);
#pragma unroll
    for (int u = 0; u < 8; u++) {
        const int idx = lane + 32 * u;
        const int row = idx >> 4, ch = idx & 15;
        const uint32_t off = (uint32_t)(row * 256 + ((ch ^ (row & 7)) << 4));
        cp16(PsB + off, qgB + row * 256 + ch * 16);
    }
    cp_commit();
    cp_wait<0>();
    __syncwarp();

    uint32_t qf[8][4];
#pragma unroll
    for (int j = 0; j < 8; j++)
        ldm4(qf[j], PsB + (uint32_t)(rA * 256 + (((2 * j + sB) ^ (rA & 7)) << 4)));
    __syncthreads();

    float o[8][4];
#pragma unroll
    for (int nt = 0; nt < 8; nt++)
#pragma unroll
        for (int i = 0; i < 4; i++) o[nt][i] = 0.f;
    float m_[2] = {-1e30f, -1e30f};
    float l_[2] = {0.f, 0.f};

    for (int t = 0; t < NT; t++) {
        if (t) __syncthreads();
        if (t + 1 < NT) { loadKV(t + 1, (t + 1) & 1); cp_wait<1>(); }
        else            { cp_wait<0>(); }
        __syncthreads();

        if (t * 64 <= q0 + w * 16 + 15) {
            const uint32_t kst = sbase + (uint32_t)(t & 1) * 16384u;
            const uint32_t vst = sbase + 32768u + (uint32_t)(t & 1) * 16384u;

            float s[8][4];
#pragma unroll
            for (int nt = 0; nt < 8; nt++)
#pragma unroll
                for (int i = 0; i < 4; i++) s[nt][i] = 0.f;

#pragma unroll
            for (int ntp = 0; ntp < 4; ntp++) {
                const uint32_t ntb = kst + (uint32_t)((2 * ntp + sB) * 2048 + rB * 256);
#pragma unroll
                for (int j = 0; j < 4; j++) {
                    uint32_t kh_[4], kl_[4];
                    const int ch = 2 * j + hB;
                    ldm4(kh_, ntb + (uint32_t)((ch ^ rB) << 4));
                    ldm4(kl_, ntb + (uint32_t)(((8 + ch) ^ rB) << 4));
                    const int nt = 2 * ntp;
                    mma16(s[nt],     qf[j],     kh_[0], kh_[1]);
                    mma16(s[nt],     qf[4 + j], kh_[0], kh_[1]);
                    mma16(s[nt],     qf[j],     kl_[0], kl_[1]);
                    mma16(s[nt + 1], qf[j],     kh_[2], kh_[3]);
                    mma16(s[nt + 1], qf[4 + j], kh_[2], kh_[3]);
                    mma16(s[nt + 1], qf[j],     kl_[2], kl_[3]);
                }
            }

            if (t >= 2 * qt) {
#pragma unroll
                for (int nt = 0; nt < 8; nt++)
#pragma unroll
                    for (int i = 0; i < 4; i++) {
                        const int kg = t * 64 + nt * 8 + 2 * ctg + (i & 1);
                        const int qg = q0 + w * 16 + gID + (i >> 1) * 8;
                        if (kg > qg) s[nt][i] = -1e30f;
                    }
            }

#pragma unroll
            for (int h2 = 0; h2 < 2; h2++) {
                float rm = -1e30f;
#pragma unroll
                for (int nt = 0; nt < 8; nt++)
                    rm = fmaxf(rm, fmaxf(s[nt][2 * h2], s[nt][2 * h2 + 1]));
                rm = fmaxf(rm, __shfl_xor_sync(0xffffffffu, rm, 1));
                rm = fmaxf(rm, __shfl_xor_sync(0xffffffffu, rm, 2));
                const float mn    = fmaxf(m_[h2], rm);
                const float alpha = __expf(m_[h2] - mn);
                m_[h2] = mn;
                float rs = 0.f;
                const int prow = gID + 8 * h2;
                const int pr7  = prow & 7;
                char* prp = smem + Psoff + prow * 256 + ctg * 4;
#pragma unroll
                for (int nt = 0; nt < 8; nt++) {
                    const float p0 = __expf(s[nt][2 * h2]     - mn);
                    const float p1 = __expf(s[nt][2 * h2 + 1] - mn);
                    rs += p0 + p1;
                    uint32_t hi, lo;
                    bfsplit2(p0, p1, hi, lo);
                    *(uint32_t*)(prp + ((nt ^ pr7) << 4))       = hi;
                    *(uint32_t*)(prp + (((8 + nt) ^ pr7) << 4)) = lo;
                }
                rs += __shfl_xor_sync(0xffffffffu, rs, 1);
                rs += __shfl_xor_sync(0xffffffffu, rs, 2);
                l_[h2] = l_[h2] * alpha + rs;
#pragma unroll
                for (int nt = 0; nt < 8; nt++) {
                    o[nt][2 * h2]     *= alpha;
                    o[nt][2 * h2 + 1] *= alpha;
                }
            }
            __syncwarp();

#pragma unroll
            for (int j = 0; j < 4; j++) {
                uint32_t ph_[4], pl_[4];
                ldm4(ph_, PsB + (uint32_t)(rA * 256 + (((2 * j + sB) ^ (rA & 7)) << 4)));
                ldm4(pl_, PsB + (uint32_t)(rA * 256 + (((8 + 2 * j + sB) ^ (rA & 7)) << 4)));
                const uint32_t jrow = vst + (uint32_t)((2 * j + hB) * 2048 + rB * 256);
#pragma unroll
                for (int ntp = 0; ntp < 4; ntp++) {
                    uint32_t vh_[4], vl_[4];
                    const int cv = 2 * ntp + sB;
                    ldm4t(vh_, jrow + (uint32_t)((cv ^ rB) << 4));
                    ldm4t(vl_, jrow + (uint32_t)(((8 + cv) ^ rB) << 4));
                    const int nt = 2 * ntp;
                    mma16(o[nt],     ph_, vh_[0], vh_[1]);
                    mma16(o[nt],     pl_, vh_[0], vh_[1]);
                    mma16(o[nt],     ph_, vl_[0], vl_[1]);
                    mma16(o[nt + 1], ph_, vh_[2], vh_[3]);
                    mma16(o[nt + 1], pl_, vh_[2], vh_[3]);
                    mma16(o[nt + 1], ph_, vl_[2], vl_[3]);
                }
            }
        }
    }

    // normalize + tf32-round (feeds the LDSM-based output GEMM), write [b,s,d]
    const int hh = bh & 15;
    const int bb = bh >> 4;
    const float i0 = 1.f / l_[0];
    const float i1 = 1.f / l_[1];
    const int qg0 = q0 + w * 16 + gID;
#pragma unroll
    for (int nt = 0; nt < 8; nt++) {
        const int d0 = hh * 64 + nt * 8 + 2 * ctg;
        *(float2*)&g_att[(size_t)(bb * SS + qg0) * DD + d0] =
            make_float2(tf32r(o[nt][0] * i0), tf32r(o[nt][1] * i0));
        *(float2*)&g_att[(size_t)(bb * SS + qg0 + 8) * DD + d0] =
            make_float2(tf32r(o[nt][2] * i1), tf32r(o[nt][3] * i1));
    }
}

// ---------------------------------------------------------------------------

extern "C" void kernel_launch(void* const* d_in, const int* in_sizes, int n_in,
                              void* d_out, int out_size)
{
    const float* x  = (const float*)d_in[0];
    const float* Wk = (const float*)d_in[1];
    const float* Wq = (const float*)d_in[2];
    const float* Wv = (const float*)d_in[3];
    const float* Wo = (const float*)d_in[4];
    const float* bo = (const float*)d_in[5];
    float* out = (float*)d_out;

    cudaFuncSetAttribute(attn_tc,
                         cudaFuncAttributeMaxDynamicSharedMemorySize, ATTN_SMEM);
    cudaFuncSetAttribute(gemm_tc<0>,
                         cudaFuncAttributeMaxDynamicSharedMemorySize, GEMM_SMEM);
    cudaFuncSetAttribute(gemm_tc<1>,
                         cudaFuncAttributeMaxDynamicSharedMemorySize, GEMM_SMEM);

    // 0) tf32 pre-round x and weights (g_wr order: Wq, Wk, Wv, Wo)
    round_conv<<<12288, 256>>>(x, Wq, Wk, Wv, Wo);

    // 1) QKV projections -> bf16 hi/lo split operands (q pre-scaled 0.125)
    gemm_tc<1><<<dim3(BB * SS / 128, DD / 128, 3), 256, GEMM_SMEM>>>(
        nullptr, nullptr);

    // 2) Tensor-core causal flash attention (bf16 Karatsuba) -> g_att [b,s,d]
    attn_tc<<<dim3(SS / 128, BB * HH), 256, ATTN_SMEM>>>();

    // 3) Output projection: out = g_att @ Wo^T + bo
    gemm_tc<0><<<dim3(BB * SS / 128, DD / 128, 1), 256, GEMM_SMEM>>>(bo, out);
}

// round 8
// speedup vs baseline: 4.2817x; 1.0055x over previous
#include <cuda_runtime.h>
#include <cuda_bf16.h>
#include <cstdint>

static constexpr int BB  = 4;
static constexpr int SS  = 2048;
static constexpr int DD  = 1024;
static constexpr int HH  = 16;
static constexpr int HSZ = 64;

// Scratch. q/k/v as bf16 hi/lo split, layout [b*h][row][128]:
//   cols 0-63 = hi(headdim), cols 64-127 = lo(headdim). Row = 256 B.
__device__ uint16_t g_qs[BB * HH * SS * 128];
__device__ uint16_t g_ks[BB * HH * SS * 128];
__device__ uint16_t g_vs[BB * HH * SS * 128];
__device__ float    g_att[BB * SS * DD];     // attention out, tf32-pre-rounded
__device__ float    g_xr[BB * SS * DD];      // x, tf32-pre-rounded
__device__ float    g_wr[4 * DD * DD];       // Wq|Wk|Wv|Wo, tf32-pre-rounded

// ---------------------------------------------------------------------------
// Helpers (sm_80-era PTX only: valid on plain compute_103)
// ---------------------------------------------------------------------------
__device__ __forceinline__ uint32_t smem_u32(const void* p) {
    uint32_t a;
    asm("{ .reg .u64 t; cvta.to.shared.u64 t, %1; cvt.u32.u64 %0, t; }"
        : "=r"(a) : "l"(p));
    return a;
}
__device__ __forceinline__ void cp16(uint32_t dst, const void* src) {
    asm volatile("cp.async.cg.shared.global [%0], [%1], 16;"
                 :: "r"(dst), "l"(src));
}
__device__ __forceinline__ void cp_commit() {
    asm volatile("cp.async.commit_group;" ::: "memory");
}
template <int N>
__device__ __forceinline__ void cp_wait() {
    asm volatile("cp.async.wait_group %0;" :: "n"(N) : "memory");
}
__device__ __forceinline__ float tf32r(float v) {
    uint32_t t;
    asm("cvt.rna.tf32.f32 %0, %1;" : "=r"(t) : "f"(v));
    return __uint_as_float(t);
}
__device__ __forceinline__ void mma_tf32(float& c0, float& c1, float& c2, float& c3,
                                         uint32_t a0, uint32_t a1, uint32_t a2, uint32_t a3,
                                         uint32_t b0, uint32_t b1) {
    asm volatile(
        "mma.sync.aligned.m16n8k8.row.col.f32.tf32.tf32.f32 "
        "{%0,%1,%2,%3}, {%4,%5,%6,%7}, {%8,%9}, {%0,%1,%2,%3};"
        : "+f"(c0), "+f"(c1), "+f"(c2), "+f"(c3)
        : "r"(a0), "r"(a1), "r"(a2), "r"(a3), "r"(b0), "r"(b1));
}
__device__ __forceinline__ void mma16(float* c, const uint32_t* a,
                                      uint32_t b0, uint32_t b1) {
    asm volatile(
        "mma.sync.aligned.m16n8k16.row.col.f32.bf16.bf16.f32 "
        "{%0,%1,%2,%3}, {%4,%5,%6,%7}, {%8,%9}, {%0,%1,%2,%3};"
        : "+f"(c[0]), "+f"(c[1]), "+f"(c[2]), "+f"(c[3])
        : "r"(a[0]), "r"(a[1]), "r"(a[2]), "r"(a[3]), "r"(b0), "r"(b1));
}
__device__ __forceinline__ void ldm4(uint32_t* r, uint32_t a) {
    asm volatile("ldmatrix.sync.aligned.m8n8.x4.shared.b16 {%0,%1,%2,%3}, [%4];"
                 : "=r"(r[0]), "=r"(r[1]), "=r"(r[2]), "=r"(r[3]) : "r"(a));
}
__device__ __forceinline__ void ldm4t(uint32_t* r, uint32_t a) {
    asm volatile("ldmatrix.sync.aligned.m8n8.x4.trans.shared.b16 {%0,%1,%2,%3}, [%4];"
                 : "=r"(r[0]), "=r"(r[1]), "=r"(r[2]), "=r"(r[3]) : "r"(a));
}
// bf16 hi/lo split of two floats, packed (elem0 low bits)
__device__ __forceinline__ void bfsplit2(float v0, float v1,
                                         uint32_t& hi, uint32_t& lo) {
    __nv_bfloat16 h0 = __float2bfloat16_rn(v0);
    __nv_bfloat16 h1 = __float2bfloat16_rn(v1);
    __nv_bfloat16 l0 = __float2bfloat16_rn(v0 - __bfloat162float(h0));
    __nv_bfloat16 l1 = __float2bfloat16_rn(v1 - __bfloat162float(h1));
    hi = (uint32_t)__bfloat16_as_ushort(h0) | ((uint32_t)__bfloat16_as_ushort(h1) << 16);
    lo = (uint32_t)__bfloat16_as_ushort(l0) | ((uint32_t)__bfloat16_as_ushort(l1) << 16);
}

// ---------------------------------------------------------------------------
// Pre-rounding: x and the four W matrices -> tf32-rounded fp32 copies.
// ---------------------------------------------------------------------------
__global__ __launch_bounds__(256)
void round_conv(const float* __restrict__ x,  const float* __restrict__ Wq,
                const float* __restrict__ Wk, const float* __restrict__ Wv,
                const float* __restrict__ Wo)
{
    const int idx = blockIdx.x * 256 + threadIdx.x;
    const float4* src;
    float4* dst;
    if (idx < 2097152) {                       // x: 8,388,608 floats
        src = (const float4*)x + idx;
        dst = (float4*)g_xr + idx;
    } else {
        const int wi  = idx - 2097152;
        const int z   = wi >> 18;              // 262,144 float4 per W
        const int off = wi & 262143;
        const float* w = (z == 0) ? Wq : (z == 1) ? Wk : (z == 2) ? Wv : Wo;
        src = (const float4*)w + off;
        dst = (float4*)g_wr + (size_t)z * 262144 + off;
    }
    float4 v = *src;
    v.x = tf32r(v.x); v.y = tf32r(v.y); v.z = tf32r(v.z); v.w = tf32r(v.w);
    *dst = v;
}

// ---------------------------------------------------------------------------
// tf32 mma.sync GEMM, ldmatrix fragment feed (validated R7). C = A @ W^T.
// MODE 0: A=g_att, W=g_wr[3], +bias, writes Cout fp32.
// MODE 1: A=g_xr, z selects g_wr[z]; epilogue bf16-splits into g_qs/ks/vs.
// ---------------------------------------------------------------------------
static constexpr int GSTAGES   = 3;
static constexpr int NCHUNK    = 32;
static constexpr int STAGE_FL  = 2 * 128 * 32;
static constexpr int GEMM_SMEM = GSTAGES * STAGE_FL * 4;  // 98304 B

template <int MODE>
__global__ __launch_bounds__(256, 2)
void gemm_tc(const float* __restrict__ bias, float* __restrict__ Cout)
{
    extern __shared__ float smf[];
    const uint32_t sbase = smem_u32(smf);

    const int tid  = threadIdx.x;
    const int wid  = tid >> 5;
    const int lane = tid & 31;
    const int gID  = lane >> 2;
    const int ctg  = lane & 3;
    const int wRow = (wid & 1) * 64;
    const int wCol = (wid >> 1) * 32;

    const int brow = blockIdx.x;
    const int bcol = blockIdx.y;
    const int z    = (MODE == 0) ? 3 : blockIdx.z;

    const float* Ain = (MODE == 0) ? (const float*)g_att : (const float*)g_xr;
    const float* ap  = Ain + (size_t)(brow * 128) * DD;
    const float* wp  = (const float*)g_wr + (size_t)z * (DD * DD)
                     + (size_t)(bcol * 128) * DD;

    const int ldrow = tid >> 3;
    const int ldc16 = tid & 7;
    auto load_chunk = [&](int chunk, int stage) {
        const uint32_t aB = sbase + (uint32_t)(stage * STAGE_FL) * 4u;
        const uint32_t bB = aB + 128 * 32 * 4;
        const float* a0 = ap + chunk * 32;
        const float* w0 = wp + chunk * 32;
#pragma unroll
        for (int u = 0; u < 4; u++) {
            const int row = ldrow + 32 * u;
            const uint32_t off =
                (uint32_t)(row * 128 + ((ldc16 ^ (row & 7)) << 4));
            cp16(aB + off, a0 + (size_t)row * DD + ldc16 * 4);
            cp16(bB + off, w0 + (size_t)row * DD + ldc16 * 4);
        }
    };

    const int x7  = lane & 7;
    const int aro = x7 + ((lane >> 3) & 1) * 8;
    const int ags = lane >> 4;
    const int bro = x7 + (lane >> 4) * 8;
    const int bgs = (lane >> 3) & 1;

    float c[4][4][4];
#pragma unroll
    for (int i = 0; i < 4; i++)
#pragma unroll
        for (int j = 0; j < 4; j++)
#pragma unroll
            for (int r = 0; r < 4; r++) c[i][j][r] = 0.f;

    load_chunk(0, 0); cp_commit();
    load_chunk(1, 1); cp_commit();

    int stage = 0;
    for (int i = 0; i < NCHUNK; i++) {
        if (i + 2 < NCHUNK) {
            load_chunk(i + 2, (stage + 2) % GSTAGES);
            cp_commit();
            cp_wait<2>();
        } else {
            cp_wait<0>();
        }
        __syncthreads();

        const uint32_t sA = sbase + (uint32_t)(stage * STAGE_FL) * 4u;
        const uint32_t sB = sA + 128 * 32 * 4;
        uint32_t aBase[4], bBase[2];
#pragma unroll
        for (int mt = 0; mt < 4; mt++)
            aBase[mt] = sA + (uint32_t)((wRow + mt * 16 + aro) * 128);
#pragma unroll
        for (int ntp = 0; ntp < 2; ntp++)
            bBase[ntp] = sB + (uint32_t)((wCol + ntp * 16 + bro) * 128);

#pragma unroll
        for (int ks = 0; ks < 4; ks++) {
            uint32_t a[4][4], b[2][4];
            const uint32_t offA = (uint32_t)(((2 * ks + ags) ^ x7) << 4);
            const uint32_t offB = (uint32_t)(((2 * ks + bgs) ^ x7) << 4);
#pragma unroll
            for (int mt = 0; mt < 4; mt++) ldm4(a[mt], aBase[mt] + offA);
#pragma unroll
            for (int ntp = 0; ntp < 2; ntp++) ldm4(b[ntp], bBase[ntp] + offB);
#pragma unroll
            for (int mt = 0; mt < 4; mt++)
#pragma unroll
                for (int ntp = 0; ntp < 2; ntp++) {
                    mma_tf32(c[mt][2*ntp][0], c[mt][2*ntp][1],
                             c[mt][2*ntp][2], c[mt][2*ntp][3],
                             a[mt][0], a[mt][1], a[mt][2], a[mt][3],
                             b[ntp][0], b[ntp][1]);
                    mma_tf32(c[mt][2*ntp+1][0], c[mt][2*ntp+1][1],
                             c[mt][2*ntp+1][2], c[mt][2*ntp+1][3],
                             a[mt][0], a[mt][1], a[mt][2], a[mt][3],
                             b[ntp][2], b[ntp][3]);
                }
        }
        __syncthreads();
        stage = (stage + 1) % GSTAGES;
    }

#pragma unroll
    for (int mt = 0; mt < 4; mt++) {
#pragma unroll
        for (int half = 0; half < 2; half++) {
            const int m = brow * 128 + wRow + mt * 16 + gID + half * 8;
            if (MODE == 0) {
                float* rowp = &Cout[(size_t)m * DD + bcol * 128];
#pragma unroll
                for (int nt = 0; nt < 4; nt++) {
                    const int n = wCol + nt * 8 + ctg * 2;
                    float2 v;
                    v.x = c[mt][nt][half * 2 + 0] + bias[bcol * 128 + n];
                    v.y = c[mt][nt][half * 2 + 1] + bias[bcol * 128 + n + 1];
                    *reinterpret_cast<float2*>(&rowp[n]) = v;
                }
            } else {
                const int bb = m >> 11;
                const int s  = m & 2047;
                uint16_t* dst = (z == 0) ? g_qs : (z == 1) ? g_ks : g_vs;
                const float qs = (z == 0) ? 0.125f : 1.0f;
#pragma unroll
                for (int nt = 0; nt < 4; nt++) {
                    const int n  = bcol * 128 + wCol + nt * 8 + ctg * 2;
                    const int h  = n >> 6;
                    const int hs = n & 63;
                    uint32_t hi, lo;
                    bfsplit2(c[mt][nt][half * 2 + 0] * qs,
                             c[mt][nt][half * 2 + 1] * qs, hi, lo);
                    const size_t base =
                        ((size_t)(bb * HH + h) * SS + s) * 128 + hs;
                    *(uint32_t*)&dst[base]      = hi;
                    *(uint32_t*)&dst[base + 64] = lo;
                }
            }
        }
    }
}

// ---------------------------------------------------------------------------
// Causal flash attention, bf16 Karatsuba. R8: P stays in registers
// (S C-fragment == PV A-fragment), masked 16-key blocks skipped on diag tiles.
// smem: K[2][64x256B] | V[2][64x256B] | Qstage[8 warps][16x256B] = 96 KB.
// ---------------------------------------------------------------------------
static constexpr int ATTN_SMEM = 98304;

__global__ __launch_bounds__(256)
void attn_tc()
{
    extern __shared__ char smem[];
    const uint32_t sbase = smem_u32(smem);

    const int tid  = threadIdx.x;
    const int w    = tid >> 5;
    const int lane = tid & 31;
    const int gID  = lane >> 2;
    const int ctg  = lane & 3;

    const int qt = (int)gridDim.x - 1 - (int)blockIdx.x;  // heavy tiles first
    const int bh = blockIdx.y;
    const int q0 = qt * 128;
    const int NT = 2 * qt + 2;

    const char* kgB = (const char*)g_ks + (size_t)bh * SS * 256;
    const char* vgB = (const char*)g_vs + (size_t)bh * SS * 256;
    const char* qgB = (const char*)g_qs + (size_t)(bh * SS + q0 + w * 16) * 256;

    const uint32_t PsB = sbase + 65536u + (uint32_t)w * 4096u;

    const int rB = lane & 7;
    const int hB = (lane >> 3) & 1;
    const int sB = lane >> 4;
    const int rA = lane & 15;

    auto loadKV = [&](int t, int st) {
        const uint32_t kb = sbase + (uint32_t)st * 16384u;
        const uint32_t vb = sbase + 32768u + (uint32_t)st * 16384u;
        const char* kp = kgB + (size_t)t * 64 * 256;
        const char* vp = vgB + (size_t)t * 64 * 256;
#pragma unroll
        for (int u = 0; u < 4; u++) {
            const int gi = tid + 256 * u;
            const int row = gi >> 4, ch = gi & 15;
            const uint32_t off = (uint32_t)(row * 256 + ((ch ^ (row & 7)) << 4));
            cp16(kb + off, kp + row * 256 + ch * 16);
            cp16(vb + off, vp + row * 256 + ch * 16);
        }
        cp_commit();
    };

    loadKV(0, 0);
    // stage Q through this warp's private region (read once into registers)
#pragma unroll
    for (int u = 0; u < 8; u++) {
        const int idx = lane + 32 * u;
        const int row = idx >> 4, ch = idx & 15;
        const uint32_t off = (uint32_t)(row * 256 + ((ch ^ (row & 7)) << 4));
        cp16(PsB + off, qgB + row * 256 + ch * 16);
    }
    cp_commit();
    cp_wait<0>();
    __syncwarp();

    uint32_t qf[8][4];
#pragma unroll
    for (int j = 0; j < 8; j++)
        ldm4(qf[j], PsB + (uint32_t)(rA * 256 + (((2 * j + sB) ^ (rA & 7)) << 4)));
    __syncthreads();

    float o[8][4];
#pragma unroll
    for (int nt = 0; nt < 8; nt++)
#pragma unroll
        for (int i = 0; i < 4; i++) o[nt][i] = 0.f;
    float m_[2] = {-1e30f, -1e30f};
    float l_[2] = {0.f, 0.f};

    for (int t = 0; t < NT; t++) {
        if (t) __syncthreads();
        if (t + 1 < NT) { loadKV(t + 1, (t + 1) & 1); cp_wait<1>(); }
        else            { cp_wait<0>(); }
        __syncthreads();

        if (t * 64 <= q0 + w * 16 + 15) {
            const uint32_t kst = sbase + (uint32_t)(t & 1) * 16384u;
            const uint32_t vst = sbase + 32768u + (uint32_t)(t & 1) * 16384u;

            // valid 16-key blocks for this warp in this tile (diag masking)
            int ntpLim = 4;
            if (t >= 2 * qt)
                ntpLim = min(4, (q0 + 16 * w + 15 - t * 64) / 16 + 1);

            // ---- S = Q K^T : kh*(qh+ql) + kl*qh ----
            float s[8][4];
#pragma unroll
            for (int nt = 0; nt < 8; nt++)
#pragma unroll
                for (int i = 0; i < 4; i++) s[nt][i] = 0.f;

#pragma unroll
            for (int ntp = 0; ntp < 4; ntp++) {
                if (ntp >= ntpLim) continue;     // fully-masked key block
                const uint32_t ntb = kst + (uint32_t)((2 * ntp + sB) * 2048 + rB * 256);
#pragma unroll
                for (int j = 0; j < 4; j++) {
                    uint32_t kh_[4], kl_[4];
                    const int ch = 2 * j + hB;
                    ldm4(kh_, ntb + (uint32_t)((ch ^ rB) << 4));
                    ldm4(kl_, ntb + (uint32_t)(((8 + ch) ^ rB) << 4));
                    const int nt = 2 * ntp;
                    mma16(s[nt],     qf[j],     kh_[0], kh_[1]);
                    mma16(s[nt],     qf[4 + j], kh_[0], kh_[1]);
                    mma16(s[nt],     qf[j],     kl_[0], kl_[1]);
                    mma16(s[nt + 1], qf[j],     kh_[2], kh_[3]);
                    mma16(s[nt + 1], qf[4 + j], kh_[2], kh_[3]);
                    mma16(s[nt + 1], qf[j],     kl_[2], kl_[3]);
                }
            }

            // ---- causal mask (covers skipped blocks too: s=0 -> -1e30) ----
            if (t >= 2 * qt) {
#pragma unroll
                for (int nt = 0; nt < 8; nt++)
#pragma unroll
                    for (int i = 0; i < 4; i++) {
                        const int kg = t * 64 + nt * 8 + 2 * ctg + (i & 1);
                        const int qg = q0 + w * 16 + gID + (i >> 1) * 8;
                        if (kg > qg) s[nt][i] = -1e30f;
                    }
            }

            // ---- online softmax; p values stay in s[][] (C-fragment) ----
#pragma unroll
            for (int h2 = 0; h2 < 2; h2++) {
                float rm = -1e30f;
#pragma unroll
                for (int nt = 0; nt < 8; nt++)
                    rm = fmaxf(rm, fmaxf(s[nt][2 * h2], s[nt][2 * h2 + 1]));
                rm = fmaxf(rm, __shfl_xor_sync(0xffffffffu, rm, 1));
                rm = fmaxf(rm, __shfl_xor_sync(0xffffffffu, rm, 2));
                const float mn    = fmaxf(m_[h2], rm);
                const float alpha = __expf(m_[h2] - mn);
                m_[h2] = mn;
                float rs = 0.f;
#pragma unroll
                for (int nt = 0; nt < 8; nt++) {
                    const float p0 = __expf(s[nt][2 * h2]     - mn);
                    const float p1 = __expf(s[nt][2 * h2 + 1] - mn);
                    s[nt][2 * h2]     = p0;
                    s[nt][2 * h2 + 1] = p1;
                    rs += p0 + p1;
                }
                rs += __shfl_xor_sync(0xffffffffu, rs, 1);
                rs += __shfl_xor_sync(0xffffffffu, rs, 2);
                l_[h2] = l_[h2] * alpha + rs;
#pragma unroll
                for (int nt = 0; nt < 8; nt++) {
                    o[nt][2 * h2]     *= alpha;
                    o[nt][2 * h2 + 1] *= alpha;
                }
            }

            // ---- O += P V : vh*(ph+pl) + vl*ph ; P packed from registers ----
            // S C-frag (rows gID/gID+8, cols 2ctg..) == PV A-frag for K-block j:
            // a0=pack(s[2j][0..1]) a1=pack(s[2j][2..3]) a2/a3 from s[2j+1].
#pragma unroll
            for (int j = 0; j < 4; j++) {
                if (j >= ntpLim) continue;       // P == 0 there
                uint32_t ph_[4], pl_[4];
                bfsplit2(s[2*j][0],   s[2*j][1],   ph_[0], pl_[0]);
                bfsplit2(s[2*j][2],   s[2*j][3],   ph_[1], pl_[1]);
                bfsplit2(s[2*j+1][0], s[2*j+1][1], ph_[2], pl_[2]);
                bfsplit2(s[2*j+1][2], s[2*j+1][3], ph_[3], pl_[3]);
                const uint32_t jrow = vst + (uint32_t)((2 * j + hB) * 2048 + rB * 256);
#pragma unroll
                for (int ntp = 0; ntp < 4; ntp++) {
                    uint32_t vh_[4], vl_[4];
                    const int cv = 2 * ntp + sB;
                    ldm4t(vh_, jrow + (uint32_t)((cv ^ rB) << 4));
                    ldm4t(vl_, jrow + (uint32_t)(((8 + cv) ^ rB) << 4));
                    const int nt = 2 * ntp;
                    mma16(o[nt],     ph_, vh_[0], vh_[1]);
                    mma16(o[nt],     pl_, vh_[0], vh_[1]);
                    mma16(o[nt],     ph_, vl_[0], vl_[1]);
                    mma16(o[nt + 1], ph_, vh_[2], vh_[3]);
                    mma16(o[nt + 1], pl_, vh_[2], vh_[3]);
                    mma16(o[nt + 1], ph_, vl_[2], vl_[3]);
                }
            }
        }
    }

    // normalize + tf32-round (feeds the LDSM-based output GEMM), write [b,s,d]
    const int hh = bh & 15;
    const int bb = bh >> 4;
    const float i0 = 1.f / l_[0];
    const float i1 = 1.f / l_[1];
    const int qg0 = q0 + w * 16 + gID;
#pragma unroll
    for (int nt = 0; nt < 8; nt++) {
        const int d0 = hh * 64 + nt * 8 + 2 * ctg;
        *(float2*)&g_att[(size_t)(bb * SS + qg0) * DD + d0] =
            make_float2(tf32r(o[nt][0] * i0), tf32r(o[nt][1] * i0));
        *(float2*)&g_att[(size_t)(bb * SS + qg0 + 8) * DD + d0] =
            make_float2(tf32r(o[nt][2] * i1), tf32r(o[nt][3] * i1));
    }
}

// ---------------------------------------------------------------------------

extern "C" void kernel_launch(void* const* d_in, const int* in_sizes, int n_in,
                              void* d_out, int out_size)
{
    const float* x  = (const float*)d_in[0];
    const float* Wk = (const float*)d_in[1];
    const float* Wq = (const float*)d_in[2];
    const float* Wv = (const float*)d_in[3];
    const float* Wo = (const float*)d_in[4];
    const float* bo = (const float*)d_in[5];
    float* out = (float*)d_out;

    cudaFuncSetAttribute(attn_tc,
                         cudaFuncAttributeMaxDynamicSharedMemorySize, ATTN_SMEM);
    cudaFuncSetAttribute(gemm_tc<0>,
                         cudaFuncAttributeMaxDynamicSharedMemorySize, GEMM_SMEM);
    cudaFuncSetAttribute(gemm_tc<1>,
                         cudaFuncAttributeMaxDynamicSharedMemorySize, GEMM_SMEM);

    // 0) tf32 pre-round x and weights (g_wr order: Wq, Wk, Wv, Wo)
    round_conv<<<12288, 256>>>(x, Wq, Wk, Wv, Wo);

    // 1) QKV projections -> bf16 hi/lo split operands (q pre-scaled 0.125)
    gemm_tc<1><<<dim3(BB * SS / 128, DD / 128, 3), 256, GEMM_SMEM>>>(
        nullptr, nullptr);

    // 2) Tensor-core causal flash attention (bf16 Karatsuba) -> g_att [b,s,d]
    attn_tc<<<dim3(SS / 128, BB * HH), 256, ATTN_SMEM>>>();

    // 3) Output projection: out = g_att @ Wo^T + bo
    gemm_tc<0><<<dim3(BB * SS / 128, DD / 128, 1), 256, GEMM_SMEM>>>(bo, out);
}

// round 10
// speedup vs baseline: 6.0500x; 1.4130x over previous
#include <cuda_runtime.h>
#include <cuda_bf16.h>
#include <cuda_fp16.h>
#include <cstdint>

static constexpr int BB  = 4;
static constexpr int SS  = 2048;
static constexpr int DD  = 1024;
static constexpr int HH  = 16;
static constexpr int HSZ = 64;

// Scratch. q/k/v as fp16 (EXACT image of tf32-rounded values), layout
// [b*h][row][64] fp16 = 128 B rows. q pre-scaled by 0.125.
__device__ uint16_t g_qs[BB * HH * SS * 64];
__device__ uint16_t g_ks[BB * HH * SS * 64];
__device__ uint16_t g_vs[BB * HH * SS * 64];
__device__ float    g_att[BB * SS * DD];     // attention out, tf32-pre-rounded
__device__ float    g_xr[BB * SS * DD];      // x, tf32-pre-rounded
__device__ float    g_wr[4 * DD * DD];       // Wq|Wk|Wv|Wo, tf32-pre-rounded

// ---------------------------------------------------------------------------
// Helpers (sm_80-era PTX only: valid on plain compute_103)
// ---------------------------------------------------------------------------
__device__ __forceinline__ uint32_t smem_u32(const void* p) {
    uint32_t a;
    asm("{ .reg .u64 t; cvta.to.shared.u64 t, %1; cvt.u32.u64 %0, t; }"
        : "=r"(a) : "l"(p));
    return a;
}
__device__ __forceinline__ void cp16(uint32_t dst, const void* src) {
    asm volatile("cp.async.cg.shared.global [%0], [%1], 16;"
                 :: "r"(dst), "l"(src));
}
__device__ __forceinline__ void cp_commit() {
    asm volatile("cp.async.commit_group;" ::: "memory");
}
template <int N>
__device__ __forceinline__ void cp_wait() {
    asm volatile("cp.async.wait_group %0;" :: "n"(N) : "memory");
}
__device__ __forceinline__ float tf32r(float v) {
    uint32_t t;
    asm("cvt.rna.tf32.f32 %0, %1;" : "=r"(t) : "f"(v));
    return __uint_as_float(t);
}
__device__ __forceinline__ void mma_tf32(float& c0, float& c1, float& c2, float& c3,
                                         uint32_t a0, uint32_t a1, uint32_t a2, uint32_t a3,
                                         uint32_t b0, uint32_t b1) {
    asm volatile(
        "mma.sync.aligned.m16n8k8.row.col.f32.tf32.tf32.f32 "
        "{%0,%1,%2,%3}, {%4,%5,%6,%7}, {%8,%9}, {%0,%1,%2,%3};"
        : "+f"(c0), "+f"(c1), "+f"(c2), "+f"(c3)
        : "r"(a0), "r"(a1), "r"(a2), "r"(a3), "r"(b0), "r"(b1));
}
__device__ __forceinline__ void mma16h(float* c, const uint32_t* a,
                                       uint32_t b0, uint32_t b1) {
    asm volatile(
        "mma.sync.aligned.m16n8k16.row.col.f32.f16.f16.f32 "
        "{%0,%1,%2,%3}, {%4,%5,%6,%7}, {%8,%9}, {%0,%1,%2,%3};"
        : "+f"(c[0]), "+f"(c[1]), "+f"(c[2]), "+f"(c[3])
        : "r"(a[0]), "r"(a[1]), "r"(a[2]), "r"(a[3]), "r"(b0), "r"(b1));
}
__device__ __forceinline__ void ldm4(uint32_t* r, uint32_t a) {
    asm volatile("ldmatrix.sync.aligned.m8n8.x4.shared.b16 {%0,%1,%2,%3}, [%4];"
                 : "=r"(r[0]), "=r"(r[1]), "=r"(r[2]), "=r"(r[3]) : "r"(a));
}
__device__ __forceinline__ void ldm4t(uint32_t* r, uint32_t a) {
    asm volatile("ldmatrix.sync.aligned.m8n8.x4.trans.shared.b16 {%0,%1,%2,%3}, [%4];"
                 : "=r"(r[0]), "=r"(r[1]), "=r"(r[2]), "=r"(r[3]) : "r"(a));
}
__device__ __forceinline__ uint32_t h2pack(float v0, float v1) {
    __half2 h = __floats2half2_rn(v0, v1);
    return *reinterpret_cast<uint32_t*>(&h);
}

// ---------------------------------------------------------------------------
// Pre-rounding: x and the four W matrices -> tf32-rounded fp32 copies.
// ---------------------------------------------------------------------------
__global__ __launch_bounds__(256)
void round_conv(const float* __restrict__ x,  const float* __restrict__ Wq,
                const float* __restrict__ Wk, const float* __restrict__ Wv,
                const float* __restrict__ Wo)
{
    const int idx = blockIdx.x * 256 + threadIdx.x;
    const float4* src;
    float4* dst;
    if (idx < 2097152) {                       // x: 8,388,608 floats
        src = (const float4*)x + idx;
        dst = (float4*)g_xr + idx;
    } else {
        const int wi  = idx - 2097152;
        const int z   = wi >> 18;              // 262,144 float4 per W
        const int off = wi & 262143;
        const float* w = (z == 0) ? Wq : (z == 1) ? Wk : (z == 2) ? Wv : Wo;
        src = (const float4*)w + off;
        dst = (float4*)g_wr + (size_t)z * 262144 + off;
    }
    float4 v = *src;
    v.x = tf32r(v.x); v.y = tf32r(v.y); v.z = tf32r(v.z); v.w = tf32r(v.w);
    *dst = v;
}

// ---------------------------------------------------------------------------
// tf32 mma.sync GEMM, ldmatrix fragment feed (validated R7). C = A @ W^T.
// MODE 0: A=g_att, W=g_wr[3], +bias, writes Cout fp32.
// MODE 1: A=g_xr, z selects g_wr[z]; epilogue fp16-converts into g_qs/ks/vs.
// ---------------------------------------------------------------------------
static constexpr int GSTAGES   = 3;
static constexpr int NCHUNK    = 32;
static constexpr int STAGE_FL  = 2 * 128 * 32;
static constexpr int GEMM_SMEM = GSTAGES * STAGE_FL * 4;  // 98304 B

template <int MODE>
__global__ __launch_bounds__(256, 2)
void gemm_tc(const float* __restrict__ bias, float* __restrict__ Cout)
{
    extern __shared__ float smf[];
    const uint32_t sbase = smem_u32(smf);

    const int tid  = threadIdx.x;
    const int wid  = tid >> 5;
    const int lane = tid & 31;
    const int gID  = lane >> 2;
    const int ctg  = lane & 3;
    const int wRow = (wid & 1) * 64;
    const int wCol = (wid >> 1) * 32;

    const int brow = blockIdx.x;
    const int bcol = blockIdx.y;
    const int z    = (MODE == 0) ? 3 : blockIdx.z;

    const float* Ain = (MODE == 0) ? (const float*)g_att : (const float*)g_xr;
    const float* ap  = Ain + (size_t)(brow * 128) * DD;
    const float* wp  = (const float*)g_wr + (size_t)z * (DD * DD)
                     + (size_t)(bcol * 128) * DD;

    const int ldrow = tid >> 3;
    const int ldc16 = tid & 7;
    auto load_chunk = [&](int chunk, int stage) {
        const uint32_t aB = sbase + (uint32_t)(stage * STAGE_FL) * 4u;
        const uint32_t bB = aB + 128 * 32 * 4;
        const float* a0 = ap + chunk * 32;
        const float* w0 = wp + chunk * 32;
#pragma unroll
        for (int u = 0; u < 4; u++) {
            const int row = ldrow + 32 * u;
            const uint32_t off =
                (uint32_t)(row * 128 + ((ldc16 ^ (row & 7)) << 4));
            cp16(aB + off, a0 + (size_t)row * DD + ldc16 * 4);
            cp16(bB + off, w0 + (size_t)row * DD + ldc16 * 4);
        }
    };

    const int x7  = lane & 7;
    const int aro = x7 + ((lane >> 3) & 1) * 8;
    const int ags = lane >> 4;
    const int bro = x7 + (lane >> 4) * 8;
    const int bgs = (lane >> 3) & 1;

    float c[4][4][4];
#pragma unroll
    for (int i = 0; i < 4; i++)
#pragma unroll
        for (int j = 0; j < 4; j++)
#pragma unroll
            for (int r = 0; r < 4; r++) c[i][j][r] = 0.f;

    load_chunk(0, 0); cp_commit();
    load_chunk(1, 1); cp_commit();

    int stage = 0;
    for (int i = 0; i < NCHUNK; i++) {
        if (i + 2 < NCHUNK) {
            load_chunk(i + 2, (stage + 2) % GSTAGES);
            cp_commit();
            cp_wait<2>();
        } else {
            cp_wait<0>();
        }
        __syncthreads();

        const uint32_t sA = sbase + (uint32_t)(stage * STAGE_FL) * 4u;
        const uint32_t sB = sA + 128 * 32 * 4;
        uint32_t aBase[4], bBase[2];
#pragma unroll
        for (int mt = 0; mt < 4; mt++)
            aBase[mt] = sA + (uint32_t)((wRow + mt * 16 + aro) * 128);
#pragma unroll
        for (int ntp = 0; ntp < 2; ntp++)
            bBase[ntp] = sB + (uint32_t)((wCol + ntp * 16 + bro) * 128);

#pragma unroll
        for (int ks = 0; ks < 4; ks++) {
            uint32_t a[4][4], b[2][4];
            const uint32_t offA = (uint32_t)(((2 * ks + ags) ^ x7) << 4);
            const uint32_t offB = (uint32_t)(((2 * ks + bgs) ^ x7) << 4);
#pragma unroll
            for (int mt = 0; mt < 4; mt++) ldm4(a[mt], aBase[mt] + offA);
#pragma unroll
            for (int ntp = 0; ntp < 2; ntp++) ldm4(b[ntp], bBase[ntp] + offB);
#pragma unroll
            for (int mt = 0; mt < 4; mt++)
#pragma unroll
                for (int ntp = 0; ntp < 2; ntp++) {
                    mma_tf32(c[mt][2*ntp][0], c[mt][2*ntp][1],
                             c[mt][2*ntp][2], c[mt][2*ntp][3],
                             a[mt][0], a[mt][1], a[mt][2], a[mt][3],
                             b[ntp][0], b[ntp][1]);
                    mma_tf32(c[mt][2*ntp+1][0], c[mt][2*ntp+1][1],
                             c[mt][2*ntp+1][2], c[mt][2*ntp+1][3],
                             a[mt][0], a[mt][1], a[mt][2], a[mt][3],
                             b[ntp][2], b[ntp][3]);
                }
        }
        __syncthreads();
        stage = (stage + 1) % GSTAGES;
    }

#pragma unroll
    for (int mt = 0; mt < 4; mt++) {
#pragma unroll
        for (int half = 0; half < 2; half++) {
            const int m = brow * 128 + wRow + mt * 16 + gID + half * 8;
            if (MODE == 0) {
                float* rowp = &Cout[(size_t)m * DD + bcol * 128];
#pragma unroll
                for (int nt = 0; nt < 4; nt++) {
                    const int n = wCol + nt * 8 + ctg * 2;
                    float2 v;
                    v.x = c[mt][nt][half * 2 + 0] + bias[bcol * 128 + n];
                    v.y = c[mt][nt][half * 2 + 1] + bias[bcol * 128 + n + 1];
                    *reinterpret_cast<float2*>(&rowp[n]) = v;
                }
            } else {
                const int bb = m >> 11;
                const int s  = m & 2047;
                uint16_t* dst = (z == 0) ? g_qs : (z == 1) ? g_ks : g_vs;
                const float qs = (z == 0) ? 0.125f : 1.0f;
#pragma unroll
                for (int nt = 0; nt < 4; nt++) {
                    const int n  = bcol * 128 + wCol + nt * 8 + ctg * 2;
                    const int h  = n >> 6;
                    const int hs = n & 63;
                    const uint32_t hv = h2pack(c[mt][nt][half * 2 + 0] * qs,
                                               c[mt][nt][half * 2 + 1] * qs);
                    *(uint32_t*)&dst[((size_t)(bb * HH + h) * SS + s) * 64 + hs] = hv;
                }
            }
        }
    }
}

// ---------------------------------------------------------------------------
// Causal flash attention, single-pass fp16 (operands are exact fp16 images of
// tf32-rounded q/k/v). 128 queries/CTA (8 warps x m16), 64-key tiles,
// 2-stage cp.async. smem: K[2][8K] | V[2][8K] | Qstage[8][2K] = 48 KB.
// ---------------------------------------------------------------------------
static constexpr int ATTN_SMEM = 49152;

__global__ __launch_bounds__(256)
void attn_tc()
{
    extern __shared__ char smem[];
    const uint32_t sbase = smem_u32(smem);

    const int tid  = threadIdx.x;
    const int w    = tid >> 5;
    const int lane = tid & 31;
    const int gID  = lane >> 2;
    const int ctg  = lane & 3;

    const int qt = (int)gridDim.x - 1 - (int)blockIdx.x;  // heavy tiles first
    const int bh = blockIdx.y;
    const int q0 = qt * 128;
    const int NT = 2 * qt + 2;

    const char* kgB = (const char*)g_ks + (size_t)bh * SS * 128;
    const char* vgB = (const char*)g_vs + (size_t)bh * SS * 128;
    const char* qgB = (const char*)g_qs + (size_t)(bh * SS + q0 + w * 16) * 128;

    const uint32_t PsB = sbase + 32768u + (uint32_t)w * 2048u;

    const int rB = lane & 7;           // row-within-8
    const int hB = (lane >> 3) & 1;    // half selector
    const int sB = lane >> 4;          // pair selector
    const int rA = lane & 15;

    auto loadKV = [&](int t, int st) {
        const uint32_t kb = sbase + (uint32_t)st * 8192u;
        const uint32_t vb = sbase + 16384u + (uint32_t)st * 8192u;
        const char* kp = kgB + (size_t)t * 64 * 128;
        const char* vp = vgB + (size_t)t * 64 * 128;
#pragma unroll
        for (int u = 0; u < 2; u++) {
            const int gi = tid + 256 * u;          // 0..511
            const int row = gi >> 3, ch = gi & 7;
            const uint32_t off = (uint32_t)(row * 128 + ((ch ^ (row & 7)) << 4));
            cp16(kb + off, kp + row * 128 + ch * 16);
            cp16(vb + off, vp + row * 128 + ch * 16);
        }
        cp_commit();
    };

    loadKV(0, 0);
    // stage Q through this warp's private region (read once into registers)
#pragma unroll
    for (int u = 0; u < 4; u++) {
        const int idx = lane + 32 * u;             // 0..127
        const int row = idx >> 3, ch = idx & 7;
        const uint32_t off = (uint32_t)(row * 128 + ((ch ^ (row & 7)) << 4));
        cp16(PsB + off, qgB + row * 128 + ch * 16);
    }
    cp_commit();
    cp_wait<0>();
    __syncwarp();

    uint32_t qf[4][4];
#pragma unroll
    for (int j = 0; j < 4; j++)
        ldm4(qf[j], PsB + (uint32_t)(rA * 128 + (((2 * j + sB) ^ (rA & 7)) << 4)));
    __syncthreads();

    float o[8][4];
#pragma unroll
    for (int nt = 0; nt < 8; nt++)
#pragma unroll
        for (int i = 0; i < 4; i++) o[nt][i] = 0.f;
    float m_[2] = {-1e30f, -1e30f};
    float l_[2] = {0.f, 0.f};

    for (int t = 0; t < NT; t++) {
        if (t) __syncthreads();
        if (t + 1 < NT) { loadKV(t + 1, (t + 1) & 1); cp_wait<1>(); }
        else            { cp_wait<0>(); }
        __syncthreads();

        if (t * 64 <= q0 + w * 16 + 15) {
            const uint32_t kst = sbase + (uint32_t)(t & 1) * 8192u;
            const uint32_t vst = sbase + 16384u + (uint32_t)(t & 1) * 8192u;

            // valid 16-key blocks for this warp in this tile (diag masking)
            int ntpLim = 4;
            if (t >= 2 * qt)
                ntpLim = min(4, (q0 + 16 * w + 15 - t * 64) / 16 + 1);

            // ---- S = Q K^T (single fp16 pass) ----
            float s[8][4];
#pragma unroll
            for (int nt = 0; nt < 8; nt++)
#pragma unroll
                for (int i = 0; i < 4; i++) s[nt][i] = 0.f;

#pragma unroll
            for (int ntp = 0; ntp < 4; ntp++) {
                if (ntp >= ntpLim) continue;
                const uint32_t ntb = kst + (uint32_t)((2 * ntp + sB) * 1024 + rB * 128);
#pragma unroll
                for (int j = 0; j < 4; j++) {
                    uint32_t kf[4];
                    ldm4(kf, ntb + (uint32_t)(((2 * j + hB) ^ rB) << 4));
                    mma16h(s[2 * ntp],     qf[j], kf[0], kf[1]);
                    mma16h(s[2 * ntp + 1], qf[j], kf[2], kf[3]);
                }
            }

            // ---- causal mask (covers skipped blocks too: s=0 -> -1e30) ----
            if (t >= 2 * qt) {
#pragma unroll
                for (int nt = 0; nt < 8; nt++)
#pragma unroll
                    for (int i = 0; i < 4; i++) {
                        const int kg = t * 64 + nt * 8 + 2 * ctg + (i & 1);
                        const int qg = q0 + w * 16 + gID + (i >> 1) * 8;
                        if (kg > qg) s[nt][i] = -1e30f;
                    }
            }

            // ---- online softmax; p stays in s[][] (C-frag == PV A-frag) ----
#pragma unroll
            for (int h2 = 0; h2 < 2; h2++) {
                float rm = -1e30f;
#pragma unroll
                for (int nt = 0; nt < 8; nt++)
                    rm = fmaxf(rm, fmaxf(s[nt][2 * h2], s[nt][2 * h2 + 1]));
                rm = fmaxf(rm, __shfl_xor_sync(0xffffffffu, rm, 1));
                rm = fmaxf(rm, __shfl_xor_sync(0xffffffffu, rm, 2));
                const float mn    = fmaxf(m_[h2], rm);
                const float alpha = __expf(m_[h2] - mn);
                m_[h2] = mn;
                float rs = 0.f;
#pragma unroll
                for (int nt = 0; nt < 8; nt++) {
                    const float p0 = __expf(s[nt][2 * h2]     - mn);
                    const float p1 = __expf(s[nt][2 * h2 + 1] - mn);
                    s[nt][2 * h2]     = p0;
                    s[nt][2 * h2 + 1] = p1;
                    rs += p0 + p1;
                }
                rs += __shfl_xor_sync(0xffffffffu, rs, 1);
                rs += __shfl_xor_sync(0xffffffffu, rs, 2);
                l_[h2] = l_[h2] * alpha + rs;
#pragma unroll
                for (int nt = 0; nt < 8; nt++) {
                    o[nt][2 * h2]     *= alpha;
                    o[nt][2 * h2 + 1] *= alpha;
                }
            }

            // ---- O += P V (fp16 P packed from registers; V ldmatrix.trans) ----
#pragma unroll
            for (int j = 0; j < 4; j++) {
                if (j >= ntpLim) continue;       // P == 0 there
                uint32_t pf[4];
                pf[0] = h2pack(s[2*j][0],   s[2*j][1]);
                pf[1] = h2pack(s[2*j][2],   s[2*j][3]);
                pf[2] = h2pack(s[2*j+1][0], s[2*j+1][1]);
                pf[3] = h2pack(s[2*j+1][2], s[2*j+1][3]);
                const uint32_t jrow = vst + (uint32_t)((2 * j + hB) * 1024 + rB * 128);
#pragma unroll
                for (int ntp = 0; ntp < 4; ntp++) {
                    uint32_t vf[4];
                    ldm4t(vf, jrow + (uint32_t)(((2 * ntp + sB) ^ rB) << 4));
                    mma16h(o[2 * ntp],     pf, vf[0], vf[1]);
                    mma16h(o[2 * ntp + 1], pf, vf[2], vf[3]);
                }
            }
        }
    }

    // normalize + tf32-round (feeds the LDSM-based output GEMM), write [b,s,d]
    const int hh = bh & 15;
    const int bb = bh >> 4;
    const float i0 = 1.f / l_[0];
    const float i1 = 1.f / l_[1];
    const int qg0 = q0 + w * 16 + gID;
#pragma unroll
    for (int nt = 0; nt < 8; nt++) {
        const int d0 = hh * 64 + nt * 8 + 2 * ctg;
        *(float2*)&g_att[(size_t)(bb * SS + qg0) * DD + d0] =
            make_float2(tf32r(o[nt][0] * i0), tf32r(o[nt][1] * i0));
        *(float2*)&g_att[(size_t)(bb * SS + qg0 + 8) * DD + d0] =
            make_float2(tf32r(o[nt][2] * i1), tf32r(o[nt][3] * i1));
    }
}

// ---------------------------------------------------------------------------

extern "C" void kernel_launch(void* const* d_in, const int* in_sizes, int n_in,
                              void* d_out, int out_size)
{
    const float* x  = (const float*)d_in[0];
    const float* Wk = (const float*)d_in[1];
    const float* Wq = (const float*)d_in[2];
    const float* Wv = (const float*)d_in[3];
    const float* Wo = (const float*)d_in[4];
    const float* bo = (const float*)d_in[5];
    float* out = (float*)d_out;

    cudaFuncSetAttribute(attn_tc,
                         cudaFuncAttributeMaxDynamicSharedMemorySize, ATTN_SMEM);
    cudaFuncSetAttribute(gemm_tc<0>,
                         cudaFuncAttributeMaxDynamicSharedMemorySize, GEMM_SMEM);
    cudaFuncSetAttribute(gemm_tc<1>,
                         cudaFuncAttributeMaxDynamicSharedMemorySize, GEMM_SMEM);

    // 0) tf32 pre-round x and weights (g_wr order: Wq, Wk, Wv, Wo)
    round_conv<<<12288, 256>>>(x, Wq, Wk, Wv, Wo);

    // 1) QKV projections -> fp16 operands (exact tf32 image; q pre-scaled)
    gemm_tc<1><<<dim3(BB * SS / 128, DD / 128, 3), 256, GEMM_SMEM>>>(
        nullptr, nullptr);

    // 2) Tensor-core causal flash attention (single-pass fp16) -> g_att
    attn_tc<<<dim3(SS / 128, BB * HH), 256, ATTN_SMEM>>>();

    // 3) Output projection: out = g_att @ Wo^T + bo
    gemm_tc<0><<<dim3(BB * SS / 128, DD / 128, 1), 256, GEMM_SMEM>>>(bo, out);
}

// round 11
// speedup vs baseline: 8.7293x; 1.4429x over previous
#include <cuda_runtime.h>
#include <cuda_fp16.h>
#include <cstdint>

static constexpr int BB  = 4;
static constexpr int SS  = 2048;
static constexpr int DD  = 1024;
static constexpr int HH  = 16;
static constexpr int HSZ = 64;

// Scratch. Everything fp16 (same 11-bit mantissa grid as tf32; fp32 accum).
// q/k/v: [b*h][row][64] fp16 = 128 B rows. q pre-scaled by 0.125.
__device__ uint16_t g_qs[BB * HH * SS * 64];
__device__ uint16_t g_ks[BB * HH * SS * 64];
__device__ uint16_t g_vs[BB * HH * SS * 64];
__device__ uint16_t g_ath[BB * SS * DD];     // attention out, fp16
__device__ uint16_t g_xh[BB * SS * DD];      // x, fp16
__device__ uint16_t g_wh[4 * DD * DD];       // Wq|Wk|Wv|Wo, fp16

// ---------------------------------------------------------------------------
// Helpers (sm_80-era PTX only: valid on plain compute_103)
// ---------------------------------------------------------------------------
__device__ __forceinline__ uint32_t smem_u32(const void* p) {
    uint32_t a;
    asm("{ .reg .u64 t; cvta.to.shared.u64 t, %1; cvt.u32.u64 %0, t; }"
        : "=r"(a) : "l"(p));
    return a;
}
__device__ __forceinline__ void cp16(uint32_t dst, const void* src) {
    asm volatile("cp.async.cg.shared.global [%0], [%1], 16;"
                 :: "r"(dst), "l"(src));
}
__device__ __forceinline__ void cp_commit() {
    asm volatile("cp.async.commit_group;" ::: "memory");
}
template <int N>
__device__ __forceinline__ void cp_wait() {
    asm volatile("cp.async.wait_group %0;" :: "n"(N) : "memory");
}
__device__ __forceinline__ void mma16h(float* c, const uint32_t* a,
                                       uint32_t b0, uint32_t b1) {
    asm volatile(
        "mma.sync.aligned.m16n8k16.row.col.f32.f16.f16.f32 "
        "{%0,%1,%2,%3}, {%4,%5,%6,%7}, {%8,%9}, {%0,%1,%2,%3};"
        : "+f"(c[0]), "+f"(c[1]), "+f"(c[2]), "+f"(c[3])
        : "r"(a[0]), "r"(a[1]), "r"(a[2]), "r"(a[3]), "r"(b0), "r"(b1));
}
__device__ __forceinline__ void ldm4(uint32_t* r, uint32_t a) {
    asm volatile("ldmatrix.sync.aligned.m8n8.x4.shared.b16 {%0,%1,%2,%3}, [%4];"
                 : "=r"(r[0]), "=r"(r[1]), "=r"(r[2]), "=r"(r[3]) : "r"(a));
}
__device__ __forceinline__ void ldm4t(uint32_t* r, uint32_t a) {
    asm volatile("ldmatrix.sync.aligned.m8n8.x4.trans.shared.b16 {%0,%1,%2,%3}, [%4];"
                 : "=r"(r[0]), "=r"(r[1]), "=r"(r[2]), "=r"(r[3]) : "r"(a));
}
__device__ __forceinline__ uint32_t h2pack(float v0, float v1) {
    __half2 h = __floats2half2_rn(v0, v1);
    return *reinterpret_cast<uint32_t*>(&h);
}

// ---------------------------------------------------------------------------
// Conversion: x and the four W matrices -> fp16 copies (one float4/thread).
// ---------------------------------------------------------------------------
__global__ __launch_bounds__(256)
void round_conv(const float* __restrict__ x,  const float* __restrict__ Wq,
                const float* __restrict__ Wk, const float* __restrict__ Wv,
                const float* __restrict__ Wo)
{
    const int idx = blockIdx.x * 256 + threadIdx.x;
    const float4* src;
    uint32_t* dst;
    if (idx < 2097152) {                       // x: 8,388,608 floats
        src = (const float4*)x + idx;
        dst = (uint32_t*)g_xh + idx * 2;
    } else {
        const int wi  = idx - 2097152;
        const int z   = wi >> 18;              // 262,144 float4 per W
        const int off = wi & 262143;
        const float* w = (z == 0) ? Wq : (z == 1) ? Wk : (z == 2) ? Wv : Wo;
        src = (const float4*)w + off;
        dst = (uint32_t*)g_wh + ((size_t)z * 262144 + off) * 2;
    }
    const float4 v = *src;
    dst[0] = h2pack(v.x, v.y);
    dst[1] = h2pack(v.z, v.w);
}

// ---------------------------------------------------------------------------
// fp16 mma.sync GEMM (fp32 accumulate), ldmatrix feed. C = A @ W^T.
// CTA 128x128, K-chunk 64 (128 B fp16 rows), 3-stage cp.async, 256 threads.
// MODE 0: A=g_ath, W=g_wh[3], +bias, writes Cout fp32.
// MODE 1: A=g_xh, z selects g_wh[z]; epilogue writes fp16 g_qs/ks/vs.
// ---------------------------------------------------------------------------
static constexpr int GSTAGES   = 3;
static constexpr int NCHUNK    = 16;                  // 1024 / 64
static constexpr int STAGE_B   = 2 * 128 * 128;       // A 16KB + B 16KB
static constexpr int GEMM_SMEM = GSTAGES * STAGE_B;   // 98304 B

template <int MODE>
__global__ __launch_bounds__(256, 2)
void gemm_tc(const float* __restrict__ bias, float* __restrict__ Cout)
{
    extern __shared__ char smch[];
    const uint32_t sbase = smem_u32(smch);

    const int tid  = threadIdx.x;
    const int wid  = tid >> 5;
    const int lane = tid & 31;
    const int gID  = lane >> 2;
    const int ctg  = lane & 3;
    const int wRow = (wid & 1) * 64;
    const int wCol = (wid >> 1) * 32;

    const int brow = blockIdx.x;
    const int bcol = blockIdx.y;
    const int z    = (MODE == 0) ? 3 : blockIdx.z;

    const uint16_t* Ain = (MODE == 0) ? g_ath : g_xh;
    const char* ap = (const char*)(Ain + (size_t)(brow * 128) * DD);
    const char* wp = (const char*)(g_wh + (size_t)z * (DD * DD)
                                        + (size_t)(bcol * 128) * DD);

    // ldmatrix lane constants
    const int rA = lane & 15;          // A row-in-16
    const int sB = lane >> 4;          // granule-half selector (A) / row-group (B)
    const int rB = lane & 7;           // B row-within-8
    const int hB = (lane >> 3) & 1;    // B granule-half selector

    auto load_chunk = [&](int chunk, int stage) {
        const uint32_t aB = sbase + (uint32_t)(stage * STAGE_B);
        const uint32_t bB = aB + 16384u;
        const char* a0 = ap + chunk * 128;          // 64 fp16 cols = 128 B
        const char* w0 = wp + chunk * 128;
#pragma unroll
        for (int u = 0; u < 4; u++) {
            const int gi  = tid + 256 * u;          // 0..1023
            const int row = gi >> 3;
            const int ch  = gi & 7;
            const uint32_t off =
                (uint32_t)(row * 128 + ((ch ^ (row & 7)) << 4));
            cp16(aB + off, a0 + (size_t)row * 2048 + ch * 16);
            cp16(bB + off, w0 + (size_t)row * 2048 + ch * 16);
        }
        cp_commit();
    };

    float c[4][4][4];
#pragma unroll
    for (int i = 0; i < 4; i++)
#pragma unroll
        for (int j = 0; j < 4; j++)
#pragma unroll
            for (int r = 0; r < 4; r++) c[i][j][r] = 0.f;

    load_chunk(0, 0);
    load_chunk(1, 1);

    int stage = 0;
    for (int i = 0; i < NCHUNK; i++) {
        if (i + 2 < NCHUNK) {
            load_chunk(i + 2, (stage + 2) % GSTAGES);
            cp_wait<2>();
        } else {
            cp_wait<0>();
        }
        __syncthreads();

        const uint32_t sA = sbase + (uint32_t)(stage * STAGE_B);
        const uint32_t sBa = sA + 16384u;
        uint32_t aBase[4], bBase[2];
#pragma unroll
        for (int mt = 0; mt < 4; mt++)
            aBase[mt] = sA + (uint32_t)((wRow + mt * 16 + rA) * 128);
#pragma unroll
        for (int ntp = 0; ntp < 2; ntp++)
            bBase[ntp] = sBa + (uint32_t)((wCol + ntp * 16 + sB * 8 + rB) * 128);

#pragma unroll
        for (int kb = 0; kb < 4; kb++) {            // 4 k16 blocks per chunk
            uint32_t a[4][4], b[2][4];
            const uint32_t offA = (uint32_t)(((2 * kb + sB) ^ (rA & 7)) << 4);
            const uint32_t offB = (uint32_t)(((2 * kb + hB) ^ rB) << 4);
#pragma unroll
            for (int mt = 0; mt < 4; mt++) ldm4(a[mt], aBase[mt] + offA);
#pragma unroll
            for (int ntp = 0; ntp < 2; ntp++) ldm4(b[ntp], bBase[ntp] + offB);
#pragma unroll
            for (int mt = 0; mt < 4; mt++)
#pragma unroll
                for (int ntp = 0; ntp < 2; ntp++) {
                    mma16h(c[mt][2 * ntp],     a[mt], b[ntp][0], b[ntp][1]);
                    mma16h(c[mt][2 * ntp + 1], a[mt], b[ntp][2], b[ntp][3]);
                }
        }
        __syncthreads();
        stage = (stage + 1) % GSTAGES;
    }

#pragma unroll
    for (int mt = 0; mt < 4; mt++) {
#pragma unroll
        for (int half = 0; half < 2; half++) {
            const int m = brow * 128 + wRow + mt * 16 + gID + half * 8;
            if (MODE == 0) {
                float* rowp = &Cout[(size_t)m * DD + bcol * 128];
#pragma unroll
                for (int nt = 0; nt < 4; nt++) {
                    const int n = wCol + nt * 8 + ctg * 2;
                    float2 v;
                    v.x = c[mt][nt][half * 2 + 0] + bias[bcol * 128 + n];
                    v.y = c[mt][nt][half * 2 + 1] + bias[bcol * 128 + n + 1];
                    *reinterpret_cast<float2*>(&rowp[n]) = v;
                }
            } else {
                const int bb = m >> 11;
                const int s  = m & 2047;
                uint16_t* dst = (z == 0) ? g_qs : (z == 1) ? g_ks : g_vs;
                const float qs = (z == 0) ? 0.125f : 1.0f;
#pragma unroll
                for (int nt = 0; nt < 4; nt++) {
                    const int n  = bcol * 128 + wCol + nt * 8 + ctg * 2;
                    const int h  = n >> 6;
                    const int hs = n & 63;
                    const uint32_t hv = h2pack(c[mt][nt][half * 2 + 0] * qs,
                                               c[mt][nt][half * 2 + 1] * qs);
                    *(uint32_t*)&dst[((size_t)(bb * HH + h) * SS + s) * 64 + hs] = hv;
                }
            }
        }
    }
}

// ---------------------------------------------------------------------------
// Causal flash attention, single-pass fp16 (validated R10). 128 queries/CTA,
// 64-key tiles, 2-stage cp.async. smem 48 KB. Epilogue writes fp16 g_ath.
// ---------------------------------------------------------------------------
static constexpr int ATTN_SMEM = 49152;

__global__ __launch_bounds__(256)
void attn_tc()
{
    extern __shared__ char smem[];
    const uint32_t sbase = smem_u32(smem);

    const int tid  = threadIdx.x;
    const int w    = tid >> 5;
    const int lane = tid & 31;
    const int gID  = lane >> 2;
    const int ctg  = lane & 3;

    const int qt = (int)gridDim.x - 1 - (int)blockIdx.x;  // heavy tiles first
    const int bh = blockIdx.y;
    const int q0 = qt * 128;
    const int NT = 2 * qt + 2;

    const char* kgB = (const char*)g_ks + (size_t)bh * SS * 128;
    const char* vgB = (const char*)g_vs + (size_t)bh * SS * 128;
    const char* qgB = (const char*)g_qs + (size_t)(bh * SS + q0 + w * 16) * 128;

    const uint32_t PsB = sbase + 32768u + (uint32_t)w * 2048u;

    const int rB = lane & 7;
    const int hB = (lane >> 3) & 1;
    const int sB = lane >> 4;
    const int rA = lane & 15;

    auto loadKV = [&](int t, int st) {
        const uint32_t kb = sbase + (uint32_t)st * 8192u;
        const uint32_t vb = sbase + 16384u + (uint32_t)st * 8192u;
        const char* kp = kgB + (size_t)t * 64 * 128;
        const char* vp = vgB + (size_t)t * 64 * 128;
#pragma unroll
        for (int u = 0; u < 2; u++) {
            const int gi = tid + 256 * u;
            const int row = gi >> 3, ch = gi & 7;
            const uint32_t off = (uint32_t)(row * 128 + ((ch ^ (row & 7)) << 4));
            cp16(kb + off, kp + row * 128 + ch * 16);
            cp16(vb + off, vp + row * 128 + ch * 16);
        }
        cp_commit();
    };

    loadKV(0, 0);
#pragma unroll
    for (int u = 0; u < 4; u++) {
        const int idx = lane + 32 * u;
        const int row = idx >> 3, ch = idx & 7;
        const uint32_t off = (uint32_t)(row * 128 + ((ch ^ (row & 7)) << 4));
        cp16(PsB + off, qgB + row * 128 + ch * 16);
    }
    cp_commit();
    cp_wait<0>();
    __syncwarp();

    uint32_t qf[4][4];
#pragma unroll
    for (int j = 0; j < 4; j++)
        ldm4(qf[j], PsB + (uint32_t)(rA * 128 + (((2 * j + sB) ^ (rA & 7)) << 4)));
    __syncthreads();

    float o[8][4];
#pragma unroll
    for (int nt = 0; nt < 8; nt++)
#pragma unroll
        for (int i = 0; i < 4; i++) o[nt][i] = 0.f;
    float m_[2] = {-1e30f, -1e30f};
    float l_[2] = {0.f, 0.f};

    for (int t = 0; t < NT; t++) {
        if (t) __syncthreads();
        if (t + 1 < NT) { loadKV(t + 1, (t + 1) & 1); cp_wait<1>(); }
        else            { cp_wait<0>(); }
        __syncthreads();

        if (t * 64 <= q0 + w * 16 + 15) {
            const uint32_t kst = sbase + (uint32_t)(t & 1) * 8192u;
            const uint32_t vst = sbase + 16384u + (uint32_t)(t & 1) * 8192u;

            int ntpLim = 4;
            if (t >= 2 * qt)
                ntpLim = min(4, (q0 + 16 * w + 15 - t * 64) / 16 + 1);

            float s[8][4];
#pragma unroll
            for (int nt = 0; nt < 8; nt++)
#pragma unroll
                for (int i = 0; i < 4; i++) s[nt][i] = 0.f;

#pragma unroll
            for (int ntp = 0; ntp < 4; ntp++) {
                if (ntp >= ntpLim) continue;
                const uint32_t ntb = kst + (uint32_t)((2 * ntp + sB) * 1024 + rB * 128);
#pragma unroll
                for (int j = 0; j < 4; j++) {
                    uint32_t kf[4];
                    ldm4(kf, ntb + (uint32_t)(((2 * j + hB) ^ rB) << 4));
                    mma16h(s[2 * ntp],     qf[j], kf[0], kf[1]);
                    mma16h(s[2 * ntp + 1], qf[j], kf[2], kf[3]);
                }
            }

            if (t >= 2 * qt) {
#pragma unroll
                for (int nt = 0; nt < 8; nt++)
#pragma unroll
                    for (int i = 0; i < 4; i++) {
                        const int kg = t * 64 + nt * 8 + 2 * ctg + (i & 1);
                        const int qg = q0 + w * 16 + gID + (i >> 1) * 8;
                        if (kg > qg) s[nt][i] = -1e30f;
                    }
            }

#pragma unroll
            for (int h2 = 0; h2 < 2; h2++) {
                float rm = -1e30f;
#pragma unroll
                for (int nt = 0; nt < 8; nt++)
                    rm = fmaxf(rm, fmaxf(s[nt][2 * h2], s[nt][2 * h2 + 1]));
                rm = fmaxf(rm, __shfl_xor_sync(0xffffffffu, rm, 1));
                rm = fmaxf(rm, __shfl_xor_sync(0xffffffffu, rm, 2));
                const float mn    = fmaxf(m_[h2], rm);
                const float alpha = __expf(m_[h2] - mn);
                m_[h2] = mn;
                float rs = 0.f;
#pragma unroll
                for (int nt = 0; nt < 8; nt++) {
                    const float p0 = __expf(s[nt][2 * h2]     - mn);
                    const float p1 = __expf(s[nt][2 * h2 + 1] - mn);
                    s[nt][2 * h2]     = p0;
                    s[nt][2 * h2 + 1] = p1;
                    rs += p0 + p1;
                }
                rs += __shfl_xor_sync(0xffffffffu, rs, 1);
                rs += __shfl_xor_sync(0xffffffffu, rs, 2);
                l_[h2] = l_[h2] * alpha + rs;
#pragma unroll
                for (int nt = 0; nt < 8; nt++) {
                    o[nt][2 * h2]     *= alpha;
                    o[nt][2 * h2 + 1] *= alpha;
                }
            }

#pragma unroll
            for (int j = 0; j < 4; j++) {
                if (j >= ntpLim) continue;
                uint32_t pf[4];
                pf[0] = h2pack(s[2*j][0],   s[2*j][1]);
                pf[1] = h2pack(s[2*j][2],   s[2*j][3]);
                pf[2] = h2pack(s[2*j+1][0], s[2*j+1][1]);
                pf[3] = h2pack(s[2*j+1][2], s[2*j+1][3]);
                const uint32_t jrow = vst + (uint32_t)((2 * j + hB) * 1024 + rB * 128);
#pragma unroll
                for (int ntp = 0; ntp < 4; ntp++) {
                    uint32_t vf[4];
                    ldm4t(vf, jrow + (uint32_t)(((2 * ntp + sB) ^ rB) << 4));
                    mma16h(o[2 * ntp],     pf, vf[0], vf[1]);
                    mma16h(o[2 * ntp + 1], pf, vf[2], vf[3]);
                }
            }
        }
    }

    // normalize, write fp16 [b, s, h*64+d] for the fp16 output GEMM
    const int hh = bh & 15;
    const int bb = bh >> 4;
    const float i0 = 1.f / l_[0];
    const float i1 = 1.f / l_[1];
    const int qg0 = q0 + w * 16 + gID;
#pragma unroll
    for (int nt = 0; nt < 8; nt++) {
        const int d0 = hh * 64 + nt * 8 + 2 * ctg;
        *(uint32_t*)&g_ath[(size_t)(bb * SS + qg0) * DD + d0] =
            h2pack(o[nt][0] * i0, o[nt][1] * i0);
        *(uint32_t*)&g_ath[(size_t)(bb * SS + qg0 + 8) * DD + d0] =
            h2pack(o[nt][2] * i1, o[nt][3] * i1);
    }
}

// ---------------------------------------------------------------------------

extern "C" void kernel_launch(void* const* d_in, const int* in_sizes, int n_in,
                              void* d_out, int out_size)
{
    const float* x  = (const float*)d_in[0];
    const float* Wk = (const float*)d_in[1];
    const float* Wq = (const float*)d_in[2];
    const float* Wv = (const float*)d_in[3];
    const float* Wo = (const float*)d_in[4];
    const float* bo = (const float*)d_in[5];
    float* out = (float*)d_out;

    cudaFuncSetAttribute(attn_tc,
                         cudaFuncAttributeMaxDynamicSharedMemorySize, ATTN_SMEM);
    cudaFuncSetAttribute(gemm_tc<0>,
                         cudaFuncAttributeMaxDynamicSharedMemorySize, GEMM_SMEM);
    cudaFuncSetAttribute(gemm_tc<1>,
                         cudaFuncAttributeMaxDynamicSharedMemorySize, GEMM_SMEM);

    // 0) fp16-convert x and weights (g_wh order: Wq, Wk, Wv, Wo)
    round_conv<<<12288, 256>>>(x, Wq, Wk, Wv, Wo);

    // 1) QKV projections (fp16 MMA, fp32 accum) -> fp16 q/k/v
    gemm_tc<1><<<dim3(BB * SS / 128, DD / 128, 3), 256, GEMM_SMEM>>>(
        nullptr, nullptr);

    // 2) Tensor-core causal flash attention (fp16) -> fp16 g_ath
    attn_tc<<<dim3(SS / 128, BB * HH), 256, ATTN_SMEM>>>();

    // 3) Output projection (fp16 MMA): out = g_ath @ Wo^T + bo
    gemm_tc<0><<<dim3(BB * SS / 128, DD / 128, 1), 256, GEMM_SMEM>>>(bo, out);
}